// round 1
// baseline (speedup 1.0000x reference)
#include <cuda_runtime.h>
#include <cstdint>
#include <cstddef>

// Problem constants
#define BATCH 8
#define CIN   256
#define KDIM  64
#define HW    4096

// ---------------------------------------------------------------------------
// Scratch (static __device__ globals: allocation-free, graph-capturable)
// ---------------------------------------------------------------------------
__device__ float g_Q [(size_t)BATCH * KDIM * HW];      //  8 MB  [b][64][4096] (flat == Qr[b][4096][64])
__device__ float g_K [(size_t)BATCH * KDIM * HW];      //  8 MB
__device__ float g_V [(size_t)BATCH * CIN  * HW];      // 33 MB  [b][256][4096]
__device__ float g_E [(size_t)BATCH * HW * HW];        // 536 MB exp(S)
__device__ float g_Zp[(size_t)BATCH * 32 * HW];        //  4 MB  per-j-tile partial row sums (deterministic, no atomics)
__device__ float g_rZ[(size_t)BATCH * HW];             // 1/Z

// ---------------------------------------------------------------------------
// Kernel 1: 1x1 conv projections.  out[b,o,p] = sum_c W[o,c]*x[b,c,p] + bias[o]
// Tile: 64 (o) x 128 (p), BK=16, 256 threads, 4x8 per thread.
// sel: 0 -> g_Q (O=64), 1 -> g_K (O=64), 2 -> g_V (O=256)
// ---------------------------------------------------------------------------
__global__ __launch_bounds__(256) void proj_kernel(
    const float* __restrict__ x, const float* __restrict__ W,
    const float* __restrict__ bias, int sel)
{
    float* out = (sel == 0) ? g_Q : (sel == 1) ? g_K : g_V;
    const int O  = (sel == 2) ? 256 : 64;
    const int b  = blockIdx.z;
    const int o0 = blockIdx.y * 64;
    const int p0 = blockIdx.x * 128;
    const int tid = threadIdx.x;
    const int ty = tid >> 4;       // 0..15
    const int tx = tid & 15;       // 0..15

    __shared__ float Wt[16][68];   // [k][o], padded
    __shared__ float Xs[16][128];  // [k][p]

    float acc[4][8];
#pragma unroll
    for (int m = 0; m < 4; m++)
#pragma unroll
        for (int n = 0; n < 8; n++) acc[m][n] = 0.0f;

    const float* xb = x + (size_t)b * CIN * HW;

    for (int c0 = 0; c0 < CIN; c0 += 16) {
        // W tile: 64 x 16, stored transposed
#pragma unroll
        for (int l = 0; l < 4; l++) {
            int e  = tid + l * 256;
            int o  = e >> 4;
            int kk = e & 15;
            Wt[kk][o] = W[(o0 + o) * CIN + c0 + kk];
        }
        // X tile: 16 x 128 (coalesced float4)
#pragma unroll
        for (int l = 0; l < 2; l++) {
            int e  = tid + l * 256;
            int kk = e >> 5;
            int p4 = (e & 31) << 2;
            float4 v = *(const float4*)(xb + (size_t)(c0 + kk) * HW + p0 + p4);
            *(float4*)(&Xs[kk][p4]) = v;
        }
        __syncthreads();
#pragma unroll
        for (int kk = 0; kk < 16; kk++) {
            float4 a  = *(const float4*)(&Wt[kk][ty * 4]);
            float4 b0 = *(const float4*)(&Xs[kk][tx * 4]);
            float4 b1 = *(const float4*)(&Xs[kk][64 + tx * 4]);
            float av[4] = {a.x, a.y, a.z, a.w};
            float bv[8] = {b0.x, b0.y, b0.z, b0.w, b1.x, b1.y, b1.z, b1.w};
#pragma unroll
            for (int m = 0; m < 4; m++)
#pragma unroll
                for (int n = 0; n < 8; n++) acc[m][n] += av[m] * bv[n];
        }
        __syncthreads();
    }

#pragma unroll
    for (int m = 0; m < 4; m++) {
        int o = o0 + ty * 4 + m;
        float bo = bias[o];
        size_t base = ((size_t)b * O + o) * HW + p0;
        float4 r0 = make_float4(acc[m][0] + bo, acc[m][1] + bo, acc[m][2] + bo, acc[m][3] + bo);
        float4 r1 = make_float4(acc[m][4] + bo, acc[m][5] + bo, acc[m][6] + bo, acc[m][7] + bo);
        *(float4*)(out + base + tx * 4)      = r0;
        *(float4*)(out + base + 64 + tx * 4) = r1;
    }
}

// ---------------------------------------------------------------------------
// Kernel 2: S = Qr @ Kr^T  (4096 x 4096, k=64), E = exp(S), partial row sums.
// Qr[i][d] = g_Q flat at i*64+d (contiguous!), same for Kr.
// Tile 128x128, BK=16, 256 threads, 8x8 per thread.
// ---------------------------------------------------------------------------
__global__ __launch_bounds__(256) void scores_kernel()
{
    const int b  = blockIdx.z;
    const int i0 = blockIdx.y * 128;
    const int j0 = blockIdx.x * 128;
    const int jt = blockIdx.x;
    const int tid = threadIdx.x;
    const int ty = tid >> 4;
    const int tx = tid & 15;

    __shared__ float Qs[16][132];  // [d][i]
    __shared__ float Ks[16][132];  // [d][j]

    float acc[8][8];
#pragma unroll
    for (int m = 0; m < 8; m++)
#pragma unroll
        for (int n = 0; n < 8; n++) acc[m][n] = 0.0f;

    const float* Qb = g_Q + (size_t)b * KDIM * HW;  // flat [4096][64]
    const float* Kb = g_K + (size_t)b * KDIM * HW;

    for (int d0 = 0; d0 < KDIM; d0 += 16) {
#pragma unroll
        for (int l = 0; l < 2; l++) {
            int e  = tid + l * 256;
            int r  = e >> 2;            // 0..127
            int dq = (e & 3) << 2;      // 0,4,8,12
            float4 qv = *(const float4*)(Qb + (size_t)(i0 + r) * 64 + d0 + dq);
            Qs[dq + 0][r] = qv.x; Qs[dq + 1][r] = qv.y;
            Qs[dq + 2][r] = qv.z; Qs[dq + 3][r] = qv.w;
            float4 kv = *(const float4*)(Kb + (size_t)(j0 + r) * 64 + d0 + dq);
            Ks[dq + 0][r] = kv.x; Ks[dq + 1][r] = kv.y;
            Ks[dq + 2][r] = kv.z; Ks[dq + 3][r] = kv.w;
        }
        __syncthreads();
#pragma unroll
        for (int kk = 0; kk < 16; kk++) {
            float4 a0 = *(const float4*)(&Qs[kk][ty * 4]);
            float4 a1 = *(const float4*)(&Qs[kk][64 + ty * 4]);
            float4 b0 = *(const float4*)(&Ks[kk][tx * 4]);
            float4 b1 = *(const float4*)(&Ks[kk][64 + tx * 4]);
            float av[8] = {a0.x, a0.y, a0.z, a0.w, a1.x, a1.y, a1.z, a1.w};
            float bv[8] = {b0.x, b0.y, b0.z, b0.w, b1.x, b1.y, b1.z, b1.w};
#pragma unroll
            for (int m = 0; m < 8; m++)
#pragma unroll
                for (int n = 0; n < 8; n++) acc[m][n] += av[m] * bv[n];
        }
        __syncthreads();
    }

    // Epilogue: exp, write E, reduce row sums across tx (16 lanes), write partials.
    const size_t Ebase = (size_t)b * HW * HW;
#pragma unroll
    for (int m = 0; m < 8; m++) {
#pragma unroll
        for (int n = 0; n < 8; n++) acc[m][n] = __expf(acc[m][n]);

        int il = (m < 4) ? (ty * 4 + m) : (64 + ty * 4 + (m - 4));
        size_t row = Ebase + (size_t)(i0 + il) * HW + j0;
        *(float4*)(g_E + row + tx * 4)      = make_float4(acc[m][0], acc[m][1], acc[m][2], acc[m][3]);
        *(float4*)(g_E + row + 64 + tx * 4) = make_float4(acc[m][4], acc[m][5], acc[m][6], acc[m][7]);

        float rs = acc[m][0] + acc[m][1] + acc[m][2] + acc[m][3]
                 + acc[m][4] + acc[m][5] + acc[m][6] + acc[m][7];
#pragma unroll
        for (int o = 1; o < 16; o <<= 1) rs += __shfl_xor_sync(0xffffffffu, rs, o);
        if (tx == 0)
            g_Zp[((size_t)(b * 32 + jt)) * HW + (i0 + il)] = rs;
    }
}

// ---------------------------------------------------------------------------
// Kernel 3: rZ[b,i] = 1 / sum_jt Zp[b,jt,i]   (deterministic reduction)
// ---------------------------------------------------------------------------
__global__ void rz_kernel()
{
    int g = blockIdx.x * blockDim.x + threadIdx.x;   // 0 .. 8*4096-1
    int b = g >> 12;
    int i = g & 4095;
    float s = 0.0f;
#pragma unroll
    for (int jt = 0; jt < 32; jt++)
        s += g_Zp[((size_t)(b * 32 + jt)) * HW + i];
    g_rZ[g] = 1.0f / s;
}

// ---------------------------------------------------------------------------
// Kernel 4: out[b,c,j] = x[b,c,j] + sum_i (V[b,c,i]*rZ[b,i]) * E[b,i,j]
// GEMM M=256(c) x N=4096(j) x K=4096(i). Tile 128x128, BK=8, 8x8/thread.
// ---------------------------------------------------------------------------
__global__ __launch_bounds__(256, 2) void out_kernel(
    const float* __restrict__ x, float* __restrict__ out)
{
    const int b  = blockIdx.z;
    const int c0 = blockIdx.y * 128;
    const int j0 = blockIdx.x * 128;
    const int tid = threadIdx.x;
    const int ty = tid >> 4;
    const int tx = tid & 15;

    __shared__ float As[8][132];   // [i][c]  (V' transposed)
    __shared__ float Bs[8][128];   // [i][j]  (E)

    float acc[8][8];
#pragma unroll
    for (int m = 0; m < 8; m++)
#pragma unroll
        for (int n = 0; n < 8; n++) acc[m][n] = 0.0f;

    const float* Vb  = g_V  + (size_t)b * CIN * HW;
    const float* Eb  = g_E  + (size_t)b * HW * HW;
    const float* rZb = g_rZ + (size_t)b * HW;

    const int cA = tid >> 1;          // 0..127
    const int k4 = (tid & 1) << 2;    // 0 or 4
    const int kB = tid >> 5;          // 0..7
    const int j4 = (tid & 31) << 2;   // 0..124

    for (int i0 = 0; i0 < HW; i0 += 8) {
        float4 v  = *(const float4*)(Vb + (size_t)(c0 + cA) * HW + i0 + k4);
        float4 rz = *(const float4*)(rZb + i0 + k4);
        As[k4 + 0][cA] = v.x * rz.x;
        As[k4 + 1][cA] = v.y * rz.y;
        As[k4 + 2][cA] = v.z * rz.z;
        As[k4 + 3][cA] = v.w * rz.w;
        float4 e = *(const float4*)(Eb + (size_t)(i0 + kB) * HW + j0 + j4);
        *(float4*)(&Bs[kB][j4]) = e;
        __syncthreads();
#pragma unroll
        for (int kk = 0; kk < 8; kk++) {
            float4 a0 = *(const float4*)(&As[kk][ty * 4]);
            float4 a1 = *(const float4*)(&As[kk][64 + ty * 4]);
            float4 b0 = *(const float4*)(&Bs[kk][tx * 4]);
            float4 b1 = *(const float4*)(&Bs[kk][64 + tx * 4]);
            float av[8] = {a0.x, a0.y, a0.z, a0.w, a1.x, a1.y, a1.z, a1.w};
            float bv[8] = {b0.x, b0.y, b0.z, b0.w, b1.x, b1.y, b1.z, b1.w};
#pragma unroll
            for (int m = 0; m < 8; m++)
#pragma unroll
                for (int n = 0; n < 8; n++) acc[m][n] += av[m] * bv[n];
        }
        __syncthreads();
    }

    // Epilogue: residual add + store
#pragma unroll
    for (int m = 0; m < 8; m++) {
        int cl = (m < 4) ? (ty * 4 + m) : (64 + ty * 4 + (m - 4));
        size_t base = ((size_t)b * CIN + (c0 + cl)) * HW + j0;
        float4 x0 = *(const float4*)(x + base + tx * 4);
        float4 x1 = *(const float4*)(x + base + 64 + tx * 4);
        float4 r0 = make_float4(acc[m][0] + x0.x, acc[m][1] + x0.y,
                                acc[m][2] + x0.z, acc[m][3] + x0.w);
        float4 r1 = make_float4(acc[m][4] + x1.x, acc[m][5] + x1.y,
                                acc[m][6] + x1.z, acc[m][7] + x1.w);
        *(float4*)(out + base + tx * 4)      = r0;
        *(float4*)(out + base + 64 + tx * 4) = r1;
    }
}

// ---------------------------------------------------------------------------
// Launch
// ---------------------------------------------------------------------------
extern "C" void kernel_launch(void* const* d_in, const int* in_sizes, int n_in,
                              void* d_out, int out_size)
{
    const float* x  = (const float*)d_in[0];
    const float* Wq = (const float*)d_in[1];
    const float* bq = (const float*)d_in[2];
    const float* Wk = (const float*)d_in[3];
    const float* bk = (const float*)d_in[4];
    const float* Wv = (const float*)d_in[5];
    const float* bv = (const float*)d_in[6];
    float* out = (float*)d_out;

    dim3 blk(256);
    proj_kernel<<<dim3(32, 1, BATCH), blk>>>(x, Wq, bq, 0);
    proj_kernel<<<dim3(32, 1, BATCH), blk>>>(x, Wk, bk, 1);
    proj_kernel<<<dim3(32, 4, BATCH), blk>>>(x, Wv, bv, 2);
    scores_kernel<<<dim3(32, 32, BATCH), blk>>>();
    rz_kernel<<<dim3(128), blk>>>();
    out_kernel<<<dim3(32, 2, BATCH), blk>>>(x, out);
}

// round 3
// speedup vs baseline: 2.0309x; 2.0309x over previous
#include <cuda_runtime.h>
#include <cstdint>
#include <cstddef>

// Problem constants
#define BATCH 8
#define CIN   256
#define KDIM  64
#define HW    4096

// ---------------------------------------------------------------------------
// Scratch (static __device__ globals: allocation-free, graph-capturable)
// ---------------------------------------------------------------------------
__device__ float g_Q [(size_t)BATCH * KDIM * HW];      //  8 MB  flat == Qr[b][4096][64]
__device__ float g_K [(size_t)BATCH * KDIM * HW];      //  8 MB
__device__ float g_V [(size_t)BATCH * CIN  * HW];      // 33 MB  [b][256][4096]
__device__ float g_E [(size_t)BATCH * HW * HW];        // 536 MB exp(S)
__device__ float g_Zp[(size_t)BATCH * 32 * HW];        //  4 MB  per-j-tile partial row sums
__device__ float g_rZ[(size_t)BATCH * HW];             // 1/Z

// ---------------------------------------------------------------------------
// Kernel 1: 1x1 conv projections.  out[b,o,p] = sum_c W[o,c]*x[b,c,p] + bias[o]
// ---------------------------------------------------------------------------
__global__ __launch_bounds__(256) void proj_kernel(
    const float* __restrict__ x, const float* __restrict__ W,
    const float* __restrict__ bias, int sel)
{
    float* out = (sel == 0) ? g_Q : (sel == 1) ? g_K : g_V;
    const int O  = (sel == 2) ? 256 : 64;
    const int b  = blockIdx.z;
    const int o0 = blockIdx.y * 64;
    const int p0 = blockIdx.x * 128;
    const int tid = threadIdx.x;
    const int ty = tid >> 4;
    const int tx = tid & 15;

    __shared__ float Wt[16][68];
    __shared__ float Xs[16][128];

    float acc[4][8];
#pragma unroll
    for (int m = 0; m < 4; m++)
#pragma unroll
        for (int n = 0; n < 8; n++) acc[m][n] = 0.0f;

    const float* xb = x + (size_t)b * CIN * HW;

    for (int c0 = 0; c0 < CIN; c0 += 16) {
#pragma unroll
        for (int l = 0; l < 4; l++) {
            int e  = tid + l * 256;
            int o  = e >> 4;
            int kk = e & 15;
            Wt[kk][o] = W[(o0 + o) * CIN + c0 + kk];
        }
#pragma unroll
        for (int l = 0; l < 2; l++) {
            int e  = tid + l * 256;
            int kk = e >> 5;
            int p4 = (e & 31) << 2;
            float4 v = *(const float4*)(xb + (size_t)(c0 + kk) * HW + p0 + p4);
            *(float4*)(&Xs[kk][p4]) = v;
        }
        __syncthreads();
#pragma unroll
        for (int kk = 0; kk < 16; kk++) {
            float4 a  = *(const float4*)(&Wt[kk][ty * 4]);
            float4 b0 = *(const float4*)(&Xs[kk][tx * 4]);
            float4 b1 = *(const float4*)(&Xs[kk][64 + tx * 4]);
            float av[4] = {a.x, a.y, a.z, a.w};
            float bv[8] = {b0.x, b0.y, b0.z, b0.w, b1.x, b1.y, b1.z, b1.w};
#pragma unroll
            for (int m = 0; m < 4; m++)
#pragma unroll
                for (int n = 0; n < 8; n++) acc[m][n] += av[m] * bv[n];
        }
        __syncthreads();
    }

#pragma unroll
    for (int m = 0; m < 4; m++) {
        int o = o0 + ty * 4 + m;
        float bo = bias[o];
        size_t base = ((size_t)b * O + o) * HW + p0;
        float4 r0 = make_float4(acc[m][0] + bo, acc[m][1] + bo, acc[m][2] + bo, acc[m][3] + bo);
        float4 r1 = make_float4(acc[m][4] + bo, acc[m][5] + bo, acc[m][6] + bo, acc[m][7] + bo);
        *(float4*)(out + base + tx * 4)      = r0;
        *(float4*)(out + base + 64 + tx * 4) = r1;
    }
}

// ---------------------------------------------------------------------------
// Kernel 2: S = Qr @ Kr^T, E = exp(S), partial row sums. (fp32 — precision)
// ---------------------------------------------------------------------------
__global__ __launch_bounds__(256) void scores_kernel()
{
    const int b  = blockIdx.z;
    const int i0 = blockIdx.y * 128;
    const int j0 = blockIdx.x * 128;
    const int jt = blockIdx.x;
    const int tid = threadIdx.x;
    const int ty = tid >> 4;
    const int tx = tid & 15;

    __shared__ float Qs[16][132];
    __shared__ float Ks[16][132];

    float acc[8][8];
#pragma unroll
    for (int m = 0; m < 8; m++)
#pragma unroll
        for (int n = 0; n < 8; n++) acc[m][n] = 0.0f;

    const float* Qb = g_Q + (size_t)b * KDIM * HW;
    const float* Kb = g_K + (size_t)b * KDIM * HW;

    for (int d0 = 0; d0 < KDIM; d0 += 16) {
#pragma unroll
        for (int l = 0; l < 2; l++) {
            int e  = tid + l * 256;
            int r  = e >> 2;
            int dq = (e & 3) << 2;
            float4 qv = *(const float4*)(Qb + (size_t)(i0 + r) * 64 + d0 + dq);
            Qs[dq + 0][r] = qv.x; Qs[dq + 1][r] = qv.y;
            Qs[dq + 2][r] = qv.z; Qs[dq + 3][r] = qv.w;
            float4 kv = *(const float4*)(Kb + (size_t)(j0 + r) * 64 + d0 + dq);
            Ks[dq + 0][r] = kv.x; Ks[dq + 1][r] = kv.y;
            Ks[dq + 2][r] = kv.z; Ks[dq + 3][r] = kv.w;
        }
        __syncthreads();
#pragma unroll
        for (int kk = 0; kk < 16; kk++) {
            float4 a0 = *(const float4*)(&Qs[kk][ty * 4]);
            float4 a1 = *(const float4*)(&Qs[kk][64 + ty * 4]);
            float4 b0 = *(const float4*)(&Ks[kk][tx * 4]);
            float4 b1 = *(const float4*)(&Ks[kk][64 + tx * 4]);
            float av[8] = {a0.x, a0.y, a0.z, a0.w, a1.x, a1.y, a1.z, a1.w};
            float bv[8] = {b0.x, b0.y, b0.z, b0.w, b1.x, b1.y, b1.z, b1.w};
#pragma unroll
            for (int m = 0; m < 8; m++)
#pragma unroll
                for (int n = 0; n < 8; n++) acc[m][n] += av[m] * bv[n];
        }
        __syncthreads();
    }

    const size_t Ebase = (size_t)b * HW * HW;
#pragma unroll
    for (int m = 0; m < 8; m++) {
#pragma unroll
        for (int n = 0; n < 8; n++) acc[m][n] = __expf(acc[m][n]);

        int il = (m < 4) ? (ty * 4 + m) : (64 + ty * 4 + (m - 4));
        size_t row = Ebase + (size_t)(i0 + il) * HW + j0;
        *(float4*)(g_E + row + tx * 4)      = make_float4(acc[m][0], acc[m][1], acc[m][2], acc[m][3]);
        *(float4*)(g_E + row + 64 + tx * 4) = make_float4(acc[m][4], acc[m][5], acc[m][6], acc[m][7]);

        float rs = acc[m][0] + acc[m][1] + acc[m][2] + acc[m][3]
                 + acc[m][4] + acc[m][5] + acc[m][6] + acc[m][7];
#pragma unroll
        for (int o = 1; o < 16; o <<= 1) rs += __shfl_xor_sync(0xffffffffu, rs, o);
        if (tx == 0)
            g_Zp[((size_t)(b * 32 + jt)) * HW + (i0 + il)] = rs;
    }
}

// ---------------------------------------------------------------------------
// Kernel 3: rZ[b,i] = 1 / sum_jt Zp[b,jt,i]
// ---------------------------------------------------------------------------
__global__ void rz_kernel()
{
    int g = blockIdx.x * blockDim.x + threadIdx.x;
    int b = g >> 12;
    int i = g & 4095;
    float s = 0.0f;
#pragma unroll
    for (int jt = 0; jt < 32; jt++)
        s += g_Zp[((size_t)(b * 32 + jt)) * HW + i];
    g_rZ[g] = 1.0f / s;
}

// ---------------------------------------------------------------------------
// Kernel 3b: fold rZ into V in place:  g_V[b,c,i] *= rZ[b,i]
// (g_V is freshly rewritten by proj_kernel every launch -> deterministic)
// ---------------------------------------------------------------------------
__global__ __launch_bounds__(256) void vscale_kernel()
{
    size_t g = (size_t)blockIdx.x * blockDim.x + threadIdx.x;  // float4 index
    int i4 = (int)(g & 1023);
    int c  = (int)((g >> 10) & 255);
    int b  = (int)(g >> 18);
    size_t off = (((size_t)b * CIN + c) * HW) + (size_t)i4 * 4;
    float4 v  = *(float4*)(g_V + off);
    float4 rz = *(const float4*)(g_rZ + (size_t)b * HW + i4 * 4);
    v.x *= rz.x; v.y *= rz.y; v.z *= rz.z; v.w *= rz.w;
    *(float4*)(g_V + off) = v;
}

// ---------------------------------------------------------------------------
// Kernel 4 (tensor cores, tf32):
//   out[b,c,j] = x[b,c,j] + sum_i Vs[b,c,i] * E[b,i,j]
// CTA tile 128(c) x 128(j), BK=16, 8 warps (2x4), warp tile 64x32,
// mma.sync.m16n8k8.tf32, cp.async double-buffered STATIC smem (<48KB).
// ---------------------------------------------------------------------------
#define OUT_BK 16
#define A_STRIDE 20     // 16 + pad4 ; r*20 mod 32 distinct over 8 rows
#define B_STRIDE 136    // 128 + pad8

__device__ __forceinline__ void cp16(float* dst_smem, const float* src)
{
    uint32_t d = (uint32_t)__cvta_generic_to_shared(dst_smem);
    asm volatile("cp.async.cg.shared.global [%0], [%1], 16;\n" :: "r"(d), "l"(src));
}

__global__ __launch_bounds__(256, 2) void out_tc_kernel(
    const float* __restrict__ x, float* __restrict__ out)
{
    __shared__ float As[2][128 * A_STRIDE];   // 2*2560 floats
    __shared__ float Bs[2][OUT_BK * B_STRIDE]; // 2*2176 floats  (total 37.9KB)

    const int b  = blockIdx.z;
    const int c0 = blockIdx.y * 128;
    const int j0 = blockIdx.x * 128;
    const int tid  = threadIdx.x;
    const int lane = tid & 31;
    const int warp = tid >> 5;
    const int m_base = (warp >> 2) * 64;   // 0 or 64
    const int n_base = (warp & 3) * 32;    // 0,32,64,96

    const float* Vb = g_V + (size_t)b * CIN * HW;
    const float* Eb = g_E + (size_t)b * HW * HW;

    float acc[4][4][4];
#pragma unroll
    for (int mt = 0; mt < 4; mt++)
#pragma unroll
        for (int nt = 0; nt < 4; nt++)
#pragma unroll
            for (int r = 0; r < 4; r++) acc[mt][nt][r] = 0.0f;

    // ---- async copy of one stage (A: 128x16, B: 16x128) ----
    auto copy_stage = [&](int s, int i0) {
#pragma unroll
        for (int l = 0; l < 2; l++) {
            int idx = tid + l * 256;          // 0..511
            int r   = idx >> 2;               // 0..127
            int f4  = (idx & 3) << 2;         // 0,4,8,12
            cp16(&As[s][r * A_STRIDE + f4], Vb + (size_t)(c0 + r) * HW + i0 + f4);
        }
#pragma unroll
        for (int l = 0; l < 2; l++) {
            int idx = tid + l * 256;          // 0..511
            int k   = idx >> 5;               // 0..15
            int f4  = (idx & 31) << 2;        // 0..124
            cp16(&Bs[s][k * B_STRIDE + f4], Eb + (size_t)(i0 + k) * HW + j0 + f4);
        }
        asm volatile("cp.async.commit_group;\n");
    };

    copy_stage(0, 0);

    const int NK = HW / OUT_BK;   // 256
    for (int kt = 0; kt < NK; kt++) {
        if (kt + 1 < NK) {
            copy_stage((kt + 1) & 1, (kt + 1) * OUT_BK);
            asm volatile("cp.async.wait_group 1;\n");
        } else {
            asm volatile("cp.async.wait_group 0;\n");
        }
        __syncthreads();

        const float* Ap = As[kt & 1];
        const float* Bp = Bs[kt & 1];

#pragma unroll
        for (int k8 = 0; k8 < 2; k8++) {
            const int kk = k8 * 8;
            uint32_t af[4][4];
            uint32_t bf[4][2];
#pragma unroll
            for (int mt = 0; mt < 4; mt++) {
                int r0 = m_base + mt * 16 + (lane >> 2);
                int kc = kk + (lane & 3);
                af[mt][0] = __float_as_uint(Ap[r0 * A_STRIDE + kc]);
                af[mt][1] = __float_as_uint(Ap[(r0 + 8) * A_STRIDE + kc]);
                af[mt][2] = __float_as_uint(Ap[r0 * A_STRIDE + kc + 4]);
                af[mt][3] = __float_as_uint(Ap[(r0 + 8) * A_STRIDE + kc + 4]);
            }
#pragma unroll
            for (int nt = 0; nt < 4; nt++) {
                int cb = n_base + nt * 8 + (lane >> 2);
                int kr = kk + (lane & 3);
                bf[nt][0] = __float_as_uint(Bp[kr * B_STRIDE + cb]);
                bf[nt][1] = __float_as_uint(Bp[(kr + 4) * B_STRIDE + cb]);
            }
#pragma unroll
            for (int mt = 0; mt < 4; mt++)
#pragma unroll
                for (int nt = 0; nt < 4; nt++) {
                    asm volatile(
                        "mma.sync.aligned.m16n8k8.row.col.f32.tf32.tf32.f32 "
                        "{%0,%1,%2,%3}, {%4,%5,%6,%7}, {%8,%9}, {%0,%1,%2,%3};\n"
                        : "+f"(acc[mt][nt][0]), "+f"(acc[mt][nt][1]),
                          "+f"(acc[mt][nt][2]), "+f"(acc[mt][nt][3])
                        : "r"(af[mt][0]), "r"(af[mt][1]), "r"(af[mt][2]), "r"(af[mt][3]),
                          "r"(bf[nt][0]), "r"(bf[nt][1]));
                }
        }
        __syncthreads();
    }

    // ---- epilogue: residual add + store ----
#pragma unroll
    for (int mt = 0; mt < 4; mt++) {
        int c = c0 + m_base + mt * 16 + (lane >> 2);
#pragma unroll
        for (int nt = 0; nt < 4; nt++) {
            int j = j0 + n_base + nt * 8 + 2 * (lane & 3);
            size_t base0 = ((size_t)b * CIN + c) * HW + j;
            size_t base1 = base0 + (size_t)8 * HW;
            float2 x0 = *(const float2*)(x + base0);
            float2 x1 = *(const float2*)(x + base1);
            float2 r0 = make_float2(acc[mt][nt][0] + x0.x, acc[mt][nt][1] + x0.y);
            float2 r1 = make_float2(acc[mt][nt][2] + x1.x, acc[mt][nt][3] + x1.y);
            *(float2*)(out + base0) = r0;
            *(float2*)(out + base1) = r1;
        }
    }
}

// ---------------------------------------------------------------------------
// Launch
// ---------------------------------------------------------------------------
extern "C" void kernel_launch(void* const* d_in, const int* in_sizes, int n_in,
                              void* d_out, int out_size)
{
    const float* x  = (const float*)d_in[0];
    const float* Wq = (const float*)d_in[1];
    const float* bq = (const float*)d_in[2];
    const float* Wk = (const float*)d_in[3];
    const float* bk = (const float*)d_in[4];
    const float* Wv = (const float*)d_in[5];
    const float* bv = (const float*)d_in[6];
    float* out = (float*)d_out;

    dim3 blk(256);
    proj_kernel<<<dim3(32, 1, BATCH), blk>>>(x, Wq, bq, 0);
    proj_kernel<<<dim3(32, 1, BATCH), blk>>>(x, Wk, bk, 1);
    proj_kernel<<<dim3(32, 4, BATCH), blk>>>(x, Wv, bv, 2);
    scores_kernel<<<dim3(32, 32, BATCH), blk>>>();
    rz_kernel<<<dim3(128), blk>>>();
    vscale_kernel<<<dim3(8192), blk>>>();
    out_tc_kernel<<<dim3(32, 2, BATCH), blk>>>(x, out);
}

// round 6
// speedup vs baseline: 2.4714x; 1.2169x over previous
#include <cuda_runtime.h>
#include <cuda_bf16.h>
#include <cstdint>
#include <cstddef>

// Problem constants
#define BATCH 8
#define CIN   256
#define KDIM  64
#define HW    4096

// ---------------------------------------------------------------------------
// Scratch (static __device__ globals: allocation-free, graph-capturable)
// ---------------------------------------------------------------------------
__device__ float g_Q [(size_t)BATCH * KDIM * HW];      //  8 MB  flat == Qr[b][4096][64]
__device__ float g_K [(size_t)BATCH * KDIM * HW];      //  8 MB
__device__ float g_V [(size_t)BATCH * CIN  * HW];      // 33 MB  [b][256][4096]
__device__ float g_E [(size_t)BATCH * HW * HW];        // 536 MB exp(S)
__device__ float g_Zp[(size_t)BATCH * 32 * HW];        //  4 MB  per-j-tile partial row sums
__device__ float g_rZ[(size_t)BATCH * HW];             // 1/Z
// bf16 hi/lo splits of Q,K (flat [b][i][d], d contiguous)
__device__ __nv_bfloat16 g_Qh[(size_t)BATCH * HW * KDIM];
__device__ __nv_bfloat16 g_Ql[(size_t)BATCH * HW * KDIM];
__device__ __nv_bfloat16 g_Kh[(size_t)BATCH * HW * KDIM];
__device__ __nv_bfloat16 g_Kl[(size_t)BATCH * HW * KDIM];

// ---------------------------------------------------------------------------
// Kernel 1: 1x1 conv projections.  out[b,o,p] = sum_c W[o,c]*x[b,c,p] + bias[o]
// ---------------------------------------------------------------------------
__global__ __launch_bounds__(256) void proj_kernel(
    const float* __restrict__ x, const float* __restrict__ W,
    const float* __restrict__ bias, int sel)
{
    float* out = (sel == 0) ? g_Q : (sel == 1) ? g_K : g_V;
    const int O  = (sel == 2) ? 256 : 64;
    const int b  = blockIdx.z;
    const int o0 = blockIdx.y * 64;
    const int p0 = blockIdx.x * 128;
    const int tid = threadIdx.x;
    const int ty = tid >> 4;
    const int tx = tid & 15;

    __shared__ float Wt[16][68];
    __shared__ float Xs[16][128];

    float acc[4][8];
#pragma unroll
    for (int m = 0; m < 4; m++)
#pragma unroll
        for (int n = 0; n < 8; n++) acc[m][n] = 0.0f;

    const float* xb = x + (size_t)b * CIN * HW;

    for (int c0 = 0; c0 < CIN; c0 += 16) {
#pragma unroll
        for (int l = 0; l < 4; l++) {
            int e  = tid + l * 256;
            int o  = e >> 4;
            int kk = e & 15;
            Wt[kk][o] = W[(o0 + o) * CIN + c0 + kk];
        }
#pragma unroll
        for (int l = 0; l < 2; l++) {
            int e  = tid + l * 256;
            int kk = e >> 5;
            int p4 = (e & 31) << 2;
            float4 v = *(const float4*)(xb + (size_t)(c0 + kk) * HW + p0 + p4);
            *(float4*)(&Xs[kk][p4]) = v;
        }
        __syncthreads();
#pragma unroll
        for (int kk = 0; kk < 16; kk++) {
            float4 a  = *(const float4*)(&Wt[kk][ty * 4]);
            float4 b0 = *(const float4*)(&Xs[kk][tx * 4]);
            float4 b1 = *(const float4*)(&Xs[kk][64 + tx * 4]);
            float av[4] = {a.x, a.y, a.z, a.w};
            float bv[8] = {b0.x, b0.y, b0.z, b0.w, b1.x, b1.y, b1.z, b1.w};
#pragma unroll
            for (int m = 0; m < 4; m++)
#pragma unroll
                for (int n = 0; n < 8; n++) acc[m][n] += av[m] * bv[n];
        }
        __syncthreads();
    }

#pragma unroll
    for (int m = 0; m < 4; m++) {
        int o = o0 + ty * 4 + m;
        float bo = bias[o];
        size_t base = ((size_t)b * O + o) * HW + p0;
        float4 r0 = make_float4(acc[m][0] + bo, acc[m][1] + bo, acc[m][2] + bo, acc[m][3] + bo);
        float4 r1 = make_float4(acc[m][4] + bo, acc[m][5] + bo, acc[m][6] + bo, acc[m][7] + bo);
        *(float4*)(out + base + tx * 4)      = r0;
        *(float4*)(out + base + 64 + tx * 4) = r1;
    }
}

// ---------------------------------------------------------------------------
// Kernel 1b: split Q,K into bf16 hi/lo pairs.  x = hi + lo
// ---------------------------------------------------------------------------
__global__ __launch_bounds__(256) void split_kernel()
{
    size_t g = (size_t)blockIdx.x * blockDim.x + threadIdx.x;  // one float4 each
    size_t off = g * 4;   // < 8*4096*64 = 2097152

    float4 q = *(const float4*)(g_Q + off);
    float4 k = *(const float4*)(g_K + off);

    float qv[4] = {q.x, q.y, q.z, q.w};
    float kv[4] = {k.x, k.y, k.z, k.w};
    __nv_bfloat16 qh[4], ql[4], kh[4], kl[4];
#pragma unroll
    for (int e = 0; e < 4; e++) {
        qh[e] = __float2bfloat16_rn(qv[e]);
        ql[e] = __float2bfloat16_rn(qv[e] - __bfloat162float(qh[e]));
        kh[e] = __float2bfloat16_rn(kv[e]);
        kl[e] = __float2bfloat16_rn(kv[e] - __bfloat162float(kh[e]));
    }
    *(uint2*)(g_Qh + off) = *(uint2*)qh;
    *(uint2*)(g_Ql + off) = *(uint2*)ql;
    *(uint2*)(g_Kh + off) = *(uint2*)kh;
    *(uint2*)(g_Kl + off) = *(uint2*)kl;
}

// ---------------------------------------------------------------------------
// Kernel 2 (tensor cores, bf16 2-term split):
//   S = Q @ K^T (fp32-accurate via hi/lo), E = exp(S), partial row sums.
// CTA 128(i) x 128(j), 8 warps (2x4), warp tile 64x32, mma.m16n8k16.bf16.
// Plain smem loads (tile loads are tiny; no async machinery needed).
// ---------------------------------------------------------------------------
#define QK_STRIDE 40   // bf16 elements per smem row (80B: 16B-aligned, conflict-free)

__global__ __launch_bounds__(256) void scores_tc_kernel()
{
    __shared__ __nv_bfloat16 sQh[128][QK_STRIDE];
    __shared__ __nv_bfloat16 sQl[128][QK_STRIDE];
    __shared__ __nv_bfloat16 sKh[128][QK_STRIDE];
    __shared__ __nv_bfloat16 sKl[128][QK_STRIDE];
    __shared__ float Zbuf[128][4];

    const int b  = blockIdx.z;
    const int i0 = blockIdx.y * 128;
    const int j0 = blockIdx.x * 128;
    const int jt = blockIdx.x;
    const int tid  = threadIdx.x;
    const int lane = tid & 31;
    const int warp = tid >> 5;
    const int m_base = (warp >> 2) * 64;   // 0 or 64
    const int wn     = warp & 3;
    const int n_base = wn * 32;            // 0,32,64,96

    const __nv_bfloat16* Qh = g_Qh + (size_t)b * HW * KDIM;
    const __nv_bfloat16* Ql = g_Ql + (size_t)b * HW * KDIM;
    const __nv_bfloat16* Kh = g_Kh + (size_t)b * HW * KDIM;
    const __nv_bfloat16* Kl = g_Kl + (size_t)b * HW * KDIM;

    float acc[4][4][4];
#pragma unroll
    for (int mt = 0; mt < 4; mt++)
#pragma unroll
        for (int nt = 0; nt < 4; nt++)
#pragma unroll
            for (int r = 0; r < 4; r++) acc[mt][nt][r] = 0.0f;

    for (int d0 = 0; d0 < KDIM; d0 += 32) {
        // ---- load 128x32 bf16 tiles for Qh,Ql,Kh,Kl (uint2 = 4 bf16) ----
#pragma unroll
        for (int l = 0; l < 2; l++) {
            int idx = tid + l * 256;          // 0..511
            int r   = idx >> 2;               // 0..127
            int f8  = (idx & 3) << 3;         // 0,8,16,24
            size_t qoff = ((size_t)(i0 + r)) * KDIM + d0 + f8;
            size_t koff = ((size_t)(j0 + r)) * KDIM + d0 + f8;
            *(uint4*)(&sQh[r][f8]) = *(const uint4*)(Qh + qoff);
            *(uint4*)(&sQl[r][f8]) = *(const uint4*)(Ql + qoff);
            *(uint4*)(&sKh[r][f8]) = *(const uint4*)(Kh + koff);
            *(uint4*)(&sKl[r][f8]) = *(const uint4*)(Kl + koff);
        }
        __syncthreads();

#pragma unroll
        for (int k16 = 0; k16 < 2; k16++) {
            const int kk = k16 * 16;
            const int kc = kk + (lane & 3) * 2;
            const int rA = lane >> 2;

            uint32_t ah[4][4], al[4][4];
#pragma unroll
            for (int mt = 0; mt < 4; mt++) {
                int r0 = m_base + mt * 16 + rA;
                ah[mt][0] = *(const uint32_t*)(&sQh[r0][kc]);
                ah[mt][1] = *(const uint32_t*)(&sQh[r0 + 8][kc]);
                ah[mt][2] = *(const uint32_t*)(&sQh[r0][kc + 8]);
                ah[mt][3] = *(const uint32_t*)(&sQh[r0 + 8][kc + 8]);
                al[mt][0] = *(const uint32_t*)(&sQl[r0][kc]);
                al[mt][1] = *(const uint32_t*)(&sQl[r0 + 8][kc]);
                al[mt][2] = *(const uint32_t*)(&sQl[r0][kc + 8]);
                al[mt][3] = *(const uint32_t*)(&sQl[r0 + 8][kc + 8]);
            }
            uint32_t bh[4][2], bl[4][2];
#pragma unroll
            for (int nt = 0; nt < 4; nt++) {
                int j = n_base + nt * 8 + rA;
                bh[nt][0] = *(const uint32_t*)(&sKh[j][kc]);
                bh[nt][1] = *(const uint32_t*)(&sKh[j][kc + 8]);
                bl[nt][0] = *(const uint32_t*)(&sKl[j][kc]);
                bl[nt][1] = *(const uint32_t*)(&sKl[j][kc + 8]);
            }
#pragma unroll
            for (int mt = 0; mt < 4; mt++)
#pragma unroll
                for (int nt = 0; nt < 4; nt++) {
#define BF16MMA(AF, BF)                                                         \
    asm volatile(                                                               \
        "mma.sync.aligned.m16n8k16.row.col.f32.bf16.bf16.f32 "                  \
        "{%0,%1,%2,%3}, {%4,%5,%6,%7}, {%8,%9}, {%0,%1,%2,%3};\n"               \
        : "+f"(acc[mt][nt][0]), "+f"(acc[mt][nt][1]),                           \
          "+f"(acc[mt][nt][2]), "+f"(acc[mt][nt][3])                            \
        : "r"(AF[mt][0]), "r"(AF[mt][1]), "r"(AF[mt][2]), "r"(AF[mt][3]),       \
          "r"(BF[nt][0]), "r"(BF[nt][1]))
                    BF16MMA(ah, bh);
                    BF16MMA(ah, bl);
                    BF16MMA(al, bh);
#undef BF16MMA
                }
        }
        __syncthreads();
    }

    // ---- epilogue: exp, write E, per-row partial sums ----
    const size_t Ebase = (size_t)b * HW * HW;
    const int rA = lane >> 2;
    const int cB = (lane & 3) * 2;

#pragma unroll
    for (int mt = 0; mt < 4; mt++) {
        float rs_lo = 0.0f, rs_hi = 0.0f;
#pragma unroll
        for (int nt = 0; nt < 4; nt++) {
            float e0 = __expf(acc[mt][nt][0]);
            float e1 = __expf(acc[mt][nt][1]);
            float e2 = __expf(acc[mt][nt][2]);
            float e3 = __expf(acc[mt][nt][3]);
            int r = i0 + m_base + mt * 16 + rA;
            int j = j0 + n_base + nt * 8 + cB;
            *(float2*)(g_E + Ebase + (size_t)r * HW + j)       = make_float2(e0, e1);
            *(float2*)(g_E + Ebase + (size_t)(r + 8) * HW + j) = make_float2(e2, e3);
            rs_lo += e0 + e1;
            rs_hi += e2 + e3;
        }
        // reduce across the 4 lanes sharing a row
#pragma unroll
        for (int o = 1; o < 4; o <<= 1) {
            rs_lo += __shfl_xor_sync(0xffffffffu, rs_lo, o);
            rs_hi += __shfl_xor_sync(0xffffffffu, rs_hi, o);
        }
        if ((lane & 3) == 0) {
            Zbuf[m_base + mt * 16 + rA][wn]     = rs_lo;
            Zbuf[m_base + mt * 16 + rA + 8][wn] = rs_hi;
        }
    }
    __syncthreads();
    if (tid < 128) {
        float s = Zbuf[tid][0] + Zbuf[tid][1] + Zbuf[tid][2] + Zbuf[tid][3];
        g_Zp[((size_t)(b * 32 + jt)) * HW + (i0 + tid)] = s;
    }
}

// ---------------------------------------------------------------------------
// Kernel 3: rZ[b,i] = 1 / sum_jt Zp[b,jt,i]
// ---------------------------------------------------------------------------
__global__ void rz_kernel()
{
    int g = blockIdx.x * blockDim.x + threadIdx.x;
    int b = g >> 12;
    int i = g & 4095;
    float s = 0.0f;
#pragma unroll
    for (int jt = 0; jt < 32; jt++)
        s += g_Zp[((size_t)(b * 32 + jt)) * HW + i];
    g_rZ[g] = 1.0f / s;
}

// ---------------------------------------------------------------------------
// Kernel 3b: fold rZ into V in place:  g_V[b,c,i] *= rZ[b,i]
// ---------------------------------------------------------------------------
__global__ __launch_bounds__(256) void vscale_kernel()
{
    size_t g = (size_t)blockIdx.x * blockDim.x + threadIdx.x;  // float4 index
    int i4 = (int)(g & 1023);
    int c  = (int)((g >> 10) & 255);
    int b  = (int)(g >> 18);
    size_t off = (((size_t)b * CIN + c) * HW) + (size_t)i4 * 4;
    float4 v  = *(float4*)(g_V + off);
    float4 rz = *(const float4*)(g_rZ + (size_t)b * HW + i4 * 4);
    v.x *= rz.x; v.y *= rz.y; v.z *= rz.z; v.w *= rz.w;
    *(float4*)(g_V + off) = v;
}

// ---------------------------------------------------------------------------
// Kernel 4 (tensor cores, tf32):
//   out[b,c,j] = x[b,c,j] + sum_i Vs[b,c,i] * E[b,i,j]
// ---------------------------------------------------------------------------
#define OUT_BK 16
#define A_STRIDE 20
#define B_STRIDE 136

__device__ __forceinline__ void cp16(float* dst_smem, const float* src)
{
    uint32_t d = (uint32_t)__cvta_generic_to_shared(dst_smem);
    asm volatile("cp.async.cg.shared.global [%0], [%1], 16;\n" :: "r"(d), "l"(src));
}

__global__ __launch_bounds__(256, 2) void out_tc_kernel(
    const float* __restrict__ x, float* __restrict__ out)
{
    __shared__ float As[2][128 * A_STRIDE];
    __shared__ float Bs[2][OUT_BK * B_STRIDE];

    const int b  = blockIdx.z;
    const int c0 = blockIdx.y * 128;
    const int j0 = blockIdx.x * 128;
    const int tid  = threadIdx.x;
    const int lane = tid & 31;
    const int warp = tid >> 5;
    const int m_base = (warp >> 2) * 64;
    const int n_base = (warp & 3) * 32;

    const float* Vb = g_V + (size_t)b * CIN * HW;
    const float* Eb = g_E + (size_t)b * HW * HW;

    float acc[4][4][4];
#pragma unroll
    for (int mt = 0; mt < 4; mt++)
#pragma unroll
        for (int nt = 0; nt < 4; nt++)
#pragma unroll
            for (int r = 0; r < 4; r++) acc[mt][nt][r] = 0.0f;

    auto copy_stage = [&](int s, int i0) {
#pragma unroll
        for (int l = 0; l < 2; l++) {
            int idx = tid + l * 256;
            int r   = idx >> 2;
            int f4  = (idx & 3) << 2;
            cp16(&As[s][r * A_STRIDE + f4], Vb + (size_t)(c0 + r) * HW + i0 + f4);
        }
#pragma unroll
        for (int l = 0; l < 2; l++) {
            int idx = tid + l * 256;
            int k   = idx >> 5;
            int f4  = (idx & 31) << 2;
            cp16(&Bs[s][k * B_STRIDE + f4], Eb + (size_t)(i0 + k) * HW + j0 + f4);
        }
        asm volatile("cp.async.commit_group;\n");
    };

    copy_stage(0, 0);

    const int NK = HW / OUT_BK;   // 256
    for (int kt = 0; kt < NK; kt++) {
        if (kt + 1 < NK) {
            copy_stage((kt + 1) & 1, (kt + 1) * OUT_BK);
            asm volatile("cp.async.wait_group 1;\n");
        } else {
            asm volatile("cp.async.wait_group 0;\n");
        }
        __syncthreads();

        const float* Ap = As[kt & 1];
        const float* Bp = Bs[kt & 1];

#pragma unroll
        for (int k8 = 0; k8 < 2; k8++) {
            const int kk = k8 * 8;
            uint32_t af[4][4];
            uint32_t bf[4][2];
#pragma unroll
            for (int mt = 0; mt < 4; mt++) {
                int r0 = m_base + mt * 16 + (lane >> 2);
                int kc = kk + (lane & 3);
                af[mt][0] = __float_as_uint(Ap[r0 * A_STRIDE + kc]);
                af[mt][1] = __float_as_uint(Ap[(r0 + 8) * A_STRIDE + kc]);
                af[mt][2] = __float_as_uint(Ap[r0 * A_STRIDE + kc + 4]);
                af[mt][3] = __float_as_uint(Ap[(r0 + 8) * A_STRIDE + kc + 4]);
            }
#pragma unroll
            for (int nt = 0; nt < 4; nt++) {
                int cb = n_base + nt * 8 + (lane >> 2);
                int kr = kk + (lane & 3);
                bf[nt][0] = __float_as_uint(Bp[kr * B_STRIDE + cb]);
                bf[nt][1] = __float_as_uint(Bp[(kr + 4) * B_STRIDE + cb]);
            }
#pragma unroll
            for (int mt = 0; mt < 4; mt++)
#pragma unroll
                for (int nt = 0; nt < 4; nt++) {
                    asm volatile(
                        "mma.sync.aligned.m16n8k8.row.col.f32.tf32.tf32.f32 "
                        "{%0,%1,%2,%3}, {%4,%5,%6,%7}, {%8,%9}, {%0,%1,%2,%3};\n"
                        : "+f"(acc[mt][nt][0]), "+f"(acc[mt][nt][1]),
                          "+f"(acc[mt][nt][2]), "+f"(acc[mt][nt][3])
                        : "r"(af[mt][0]), "r"(af[mt][1]), "r"(af[mt][2]), "r"(af[mt][3]),
                          "r"(bf[nt][0]), "r"(bf[nt][1]));
                }
        }
        __syncthreads();
    }

#pragma unroll
    for (int mt = 0; mt < 4; mt++) {
        int c = c0 + m_base + mt * 16 + (lane >> 2);
#pragma unroll
        for (int nt = 0; nt < 4; nt++) {
            int j = j0 + n_base + nt * 8 + 2 * (lane & 3);
            size_t base0 = ((size_t)b * CIN + c) * HW + j;
            size_t base1 = base0 + (size_t)8 * HW;
            float2 x0 = *(const float2*)(x + base0);
            float2 x1 = *(const float2*)(x + base1);
            float2 r0 = make_float2(acc[mt][nt][0] + x0.x, acc[mt][nt][1] + x0.y);
            float2 r1 = make_float2(acc[mt][nt][2] + x1.x, acc[mt][nt][3] + x1.y);
            *(float2*)(out + base0) = r0;
            *(float2*)(out + base1) = r1;
        }
    }
}

// ---------------------------------------------------------------------------
// Launch
// ---------------------------------------------------------------------------
extern "C" void kernel_launch(void* const* d_in, const int* in_sizes, int n_in,
                              void* d_out, int out_size)
{
    const float* x  = (const float*)d_in[0];
    const float* Wq = (const float*)d_in[1];
    const float* bq = (const float*)d_in[2];
    const float* Wk = (const float*)d_in[3];
    const float* bk = (const float*)d_in[4];
    const float* Wv = (const float*)d_in[5];
    const float* bv = (const float*)d_in[6];
    float* out = (float*)d_out;

    dim3 blk(256);
    proj_kernel<<<dim3(32, 1, BATCH), blk>>>(x, Wq, bq, 0);
    proj_kernel<<<dim3(32, 1, BATCH), blk>>>(x, Wk, bk, 1);
    proj_kernel<<<dim3(32, 4, BATCH), blk>>>(x, Wv, bv, 2);
    split_kernel<<<dim3(2048), blk>>>();
    scores_tc_kernel<<<dim3(32, 32, BATCH), blk>>>();
    rz_kernel<<<dim3(128), blk>>>();
    vscale_kernel<<<dim3(8192), blk>>>();
    out_tc_kernel<<<dim3(32, 2, BATCH), blk>>>(x, out);
}

// round 9
// speedup vs baseline: 2.5861x; 1.0464x over previous
#include <cuda_runtime.h>
#include <cuda_bf16.h>
#include <cstdint>
#include <cstddef>

// Problem constants
#define BATCH 8
#define CIN   256
#define KDIM  64
#define HW    4096

// ---------------------------------------------------------------------------
// Scratch (static __device__ globals: allocation-free, graph-capturable)
// ---------------------------------------------------------------------------
__device__ float g_Q [(size_t)BATCH * KDIM * HW];      //  8 MB  flat == Qr[b][4096][64]
__device__ float g_K [(size_t)BATCH * KDIM * HW];      //  8 MB
__device__ float g_V [(size_t)BATCH * CIN  * HW];      // 33 MB  [b][256][4096]
__device__ float g_E [(size_t)BATCH * HW * HW];        // 536 MB exp(S)
__device__ float g_Zp[(size_t)BATCH * 32 * HW];        //  4 MB  per-j-tile partial row sums
__device__ float g_rZ[(size_t)BATCH * HW];             // 1/Z
// bf16 hi/lo splits of Q,K (flat [b][i][d], d contiguous)
__device__ __nv_bfloat16 g_Qh[(size_t)BATCH * HW * KDIM];
__device__ __nv_bfloat16 g_Ql[(size_t)BATCH * HW * KDIM];
__device__ __nv_bfloat16 g_Kh[(size_t)BATCH * HW * KDIM];
__device__ __nv_bfloat16 g_Kl[(size_t)BATCH * HW * KDIM];

// ---------------------------------------------------------------------------
// Kernel 1: 1x1 conv projections.  out[b,o,p] = sum_c W[o,c]*x[b,c,p] + bias[o]
// ---------------------------------------------------------------------------
__global__ __launch_bounds__(256) void proj_kernel(
    const float* __restrict__ x, const float* __restrict__ W,
    const float* __restrict__ bias, int sel)
{
    float* out = (sel == 0) ? g_Q : (sel == 1) ? g_K : g_V;
    const int O  = (sel == 2) ? 256 : 64;
    const int b  = blockIdx.z;
    const int o0 = blockIdx.y * 64;
    const int p0 = blockIdx.x * 128;
    const int tid = threadIdx.x;
    const int ty = tid >> 4;
    const int tx = tid & 15;

    __shared__ float Wt[16][68];
    __shared__ float Xs[16][128];

    float acc[4][8];
#pragma unroll
    for (int m = 0; m < 4; m++)
#pragma unroll
        for (int n = 0; n < 8; n++) acc[m][n] = 0.0f;

    const float* xb = x + (size_t)b * CIN * HW;

    for (int c0 = 0; c0 < CIN; c0 += 16) {
#pragma unroll
        for (int l = 0; l < 4; l++) {
            int e  = tid + l * 256;
            int o  = e >> 4;
            int kk = e & 15;
            Wt[kk][o] = W[(o0 + o) * CIN + c0 + kk];
        }
#pragma unroll
        for (int l = 0; l < 2; l++) {
            int e  = tid + l * 256;
            int kk = e >> 5;
            int p4 = (e & 31) << 2;
            float4 v = *(const float4*)(xb + (size_t)(c0 + kk) * HW + p0 + p4);
            *(float4*)(&Xs[kk][p4]) = v;
        }
        __syncthreads();
#pragma unroll
        for (int kk = 0; kk < 16; kk++) {
            float4 a  = *(const float4*)(&Wt[kk][ty * 4]);
            float4 b0 = *(const float4*)(&Xs[kk][tx * 4]);
            float4 b1 = *(const float4*)(&Xs[kk][64 + tx * 4]);
            float av[4] = {a.x, a.y, a.z, a.w};
            float bv[8] = {b0.x, b0.y, b0.z, b0.w, b1.x, b1.y, b1.z, b1.w};
#pragma unroll
            for (int m = 0; m < 4; m++)
#pragma unroll
                for (int n = 0; n < 8; n++) acc[m][n] += av[m] * bv[n];
        }
        __syncthreads();
    }

#pragma unroll
    for (int m = 0; m < 4; m++) {
        int o = o0 + ty * 4 + m;
        float bo = bias[o];
        size_t base = ((size_t)b * O + o) * HW + p0;
        float4 r0 = make_float4(acc[m][0] + bo, acc[m][1] + bo, acc[m][2] + bo, acc[m][3] + bo);
        float4 r1 = make_float4(acc[m][4] + bo, acc[m][5] + bo, acc[m][6] + bo, acc[m][7] + bo);
        *(float4*)(out + base + tx * 4)      = r0;
        *(float4*)(out + base + 64 + tx * 4) = r1;
    }
}

// ---------------------------------------------------------------------------
// Kernel 1b: split Q,K into bf16 hi/lo pairs.  x = hi + lo
// ---------------------------------------------------------------------------
__global__ __launch_bounds__(256) void split_kernel()
{
    size_t g = (size_t)blockIdx.x * blockDim.x + threadIdx.x;  // one float4 each
    size_t off = g * 4;   // < 8*4096*64 = 2097152

    float4 q = *(const float4*)(g_Q + off);
    float4 k = *(const float4*)(g_K + off);

    float qv[4] = {q.x, q.y, q.z, q.w};
    float kv[4] = {k.x, k.y, k.z, k.w};
    __nv_bfloat16 qh[4], ql[4], kh[4], kl[4];
#pragma unroll
    for (int e = 0; e < 4; e++) {
        qh[e] = __float2bfloat16_rn(qv[e]);
        ql[e] = __float2bfloat16_rn(qv[e] - __bfloat162float(qh[e]));
        kh[e] = __float2bfloat16_rn(kv[e]);
        kl[e] = __float2bfloat16_rn(kv[e] - __bfloat162float(kh[e]));
    }
    *(uint2*)(g_Qh + off) = *(uint2*)qh;
    *(uint2*)(g_Ql + off) = *(uint2*)ql;
    *(uint2*)(g_Kh + off) = *(uint2*)kh;
    *(uint2*)(g_Kl + off) = *(uint2*)kl;
}

// ---------------------------------------------------------------------------
// Kernel 2 (tensor cores, bf16 2-term split):
//   S = Q @ K^T (fp32-accurate via hi/lo), E = exp(S), partial row sums.
// CTA 128(i) x 128(j), 8 warps (2x4), warp tile 64x32, mma.m16n8k16.bf16.
// ---------------------------------------------------------------------------
#define QK_STRIDE 40   // bf16 elements per smem row (80B: 16B-aligned, conflict-free)

__global__ __launch_bounds__(256) void scores_tc_kernel()
{
    __shared__ __nv_bfloat16 sQh[128][QK_STRIDE];
    __shared__ __nv_bfloat16 sQl[128][QK_STRIDE];
    __shared__ __nv_bfloat16 sKh[128][QK_STRIDE];
    __shared__ __nv_bfloat16 sKl[128][QK_STRIDE];
    __shared__ float Zbuf[128][4];

    const int b  = blockIdx.z;
    const int i0 = blockIdx.y * 128;
    const int j0 = blockIdx.x * 128;
    const int jt = blockIdx.x;
    const int tid  = threadIdx.x;
    const int lane = tid & 31;
    const int warp = tid >> 5;
    const int m_base = (warp >> 2) * 64;   // 0 or 64
    const int wn     = warp & 3;
    const int n_base = wn * 32;            // 0,32,64,96

    const __nv_bfloat16* Qh = g_Qh + (size_t)b * HW * KDIM;
    const __nv_bfloat16* Ql = g_Ql + (size_t)b * HW * KDIM;
    const __nv_bfloat16* Kh = g_Kh + (size_t)b * HW * KDIM;
    const __nv_bfloat16* Kl = g_Kl + (size_t)b * HW * KDIM;

    float acc[4][4][4];
#pragma unroll
    for (int mt = 0; mt < 4; mt++)
#pragma unroll
        for (int nt = 0; nt < 4; nt++)
#pragma unroll
            for (int r = 0; r < 4; r++) acc[mt][nt][r] = 0.0f;

    for (int d0 = 0; d0 < KDIM; d0 += 32) {
        // ---- load 128x32 bf16 tiles for Qh,Ql,Kh,Kl (uint4 = 8 bf16) ----
#pragma unroll
        for (int l = 0; l < 2; l++) {
            int idx = tid + l * 256;          // 0..511
            int r   = idx >> 2;               // 0..127
            int f8  = (idx & 3) << 3;         // 0,8,16,24
            size_t qoff = ((size_t)(i0 + r)) * KDIM + d0 + f8;
            size_t koff = ((size_t)(j0 + r)) * KDIM + d0 + f8;
            *(uint4*)(&sQh[r][f8]) = *(const uint4*)(Qh + qoff);
            *(uint4*)(&sQl[r][f8]) = *(const uint4*)(Ql + qoff);
            *(uint4*)(&sKh[r][f8]) = *(const uint4*)(Kh + koff);
            *(uint4*)(&sKl[r][f8]) = *(const uint4*)(Kl + koff);
        }
        __syncthreads();

#pragma unroll
        for (int k16 = 0; k16 < 2; k16++) {
            const int kk = k16 * 16;
            const int kc = kk + (lane & 3) * 2;
            const int rA = lane >> 2;

            uint32_t ah[4][4], al[4][4];
#pragma unroll
            for (int mt = 0; mt < 4; mt++) {
                int r0 = m_base + mt * 16 + rA;
                ah[mt][0] = *(const uint32_t*)(&sQh[r0][kc]);
                ah[mt][1] = *(const uint32_t*)(&sQh[r0 + 8][kc]);
                ah[mt][2] = *(const uint32_t*)(&sQh[r0][kc + 8]);
                ah[mt][3] = *(const uint32_t*)(&sQh[r0 + 8][kc + 8]);
                al[mt][0] = *(const uint32_t*)(&sQl[r0][kc]);
                al[mt][1] = *(const uint32_t*)(&sQl[r0 + 8][kc]);
                al[mt][2] = *(const uint32_t*)(&sQl[r0][kc + 8]);
                al[mt][3] = *(const uint32_t*)(&sQl[r0 + 8][kc + 8]);
            }
            uint32_t bh[4][2], bl[4][2];
#pragma unroll
            for (int nt = 0; nt < 4; nt++) {
                int j = n_base + nt * 8 + rA;
                bh[nt][0] = *(const uint32_t*)(&sKh[j][kc]);
                bh[nt][1] = *(const uint32_t*)(&sKh[j][kc + 8]);
                bl[nt][0] = *(const uint32_t*)(&sKl[j][kc]);
                bl[nt][1] = *(const uint32_t*)(&sKl[j][kc + 8]);
            }
#pragma unroll
            for (int mt = 0; mt < 4; mt++)
#pragma unroll
                for (int nt = 0; nt < 4; nt++) {
#define BF16MMA(AF, BF)                                                         \
    asm volatile(                                                               \
        "mma.sync.aligned.m16n8k16.row.col.f32.bf16.bf16.f32 "                  \
        "{%0,%1,%2,%3}, {%4,%5,%6,%7}, {%8,%9}, {%0,%1,%2,%3};\n"               \
        : "+f"(acc[mt][nt][0]), "+f"(acc[mt][nt][1]),                           \
          "+f"(acc[mt][nt][2]), "+f"(acc[mt][nt][3])                            \
        : "r"(AF[mt][0]), "r"(AF[mt][1]), "r"(AF[mt][2]), "r"(AF[mt][3]),       \
          "r"(BF[nt][0]), "r"(BF[nt][1]))
                    BF16MMA(ah, bh);
                    BF16MMA(ah, bl);
                    BF16MMA(al, bh);
#undef BF16MMA
                }
        }
        __syncthreads();
    }

    // ---- epilogue: exp, write E, per-row partial sums ----
    const size_t Ebase = (size_t)b * HW * HW;
    const int rA = lane >> 2;
    const int cB = (lane & 3) * 2;

#pragma unroll
    for (int mt = 0; mt < 4; mt++) {
        float rs_lo = 0.0f, rs_hi = 0.0f;
#pragma unroll
        for (int nt = 0; nt < 4; nt++) {
            float e0 = __expf(acc[mt][nt][0]);
            float e1 = __expf(acc[mt][nt][1]);
            float e2 = __expf(acc[mt][nt][2]);
            float e3 = __expf(acc[mt][nt][3]);
            int r = i0 + m_base + mt * 16 + rA;
            int j = j0 + n_base + nt * 8 + cB;
            *(float2*)(g_E + Ebase + (size_t)r * HW + j)       = make_float2(e0, e1);
            *(float2*)(g_E + Ebase + (size_t)(r + 8) * HW + j) = make_float2(e2, e3);
            rs_lo += e0 + e1;
            rs_hi += e2 + e3;
        }
        // reduce across the 4 lanes sharing a row
#pragma unroll
        for (int o = 1; o < 4; o <<= 1) {
            rs_lo += __shfl_xor_sync(0xffffffffu, rs_lo, o);
            rs_hi += __shfl_xor_sync(0xffffffffu, rs_hi, o);
        }
        if ((lane & 3) == 0) {
            Zbuf[m_base + mt * 16 + rA][wn]     = rs_lo;
            Zbuf[m_base + mt * 16 + rA + 8][wn] = rs_hi;
        }
    }
    __syncthreads();
    if (tid < 128) {
        float s = Zbuf[tid][0] + Zbuf[tid][1] + Zbuf[tid][2] + Zbuf[tid][3];
        g_Zp[((size_t)(b * 32 + jt)) * HW + (i0 + tid)] = s;
    }
}

// ---------------------------------------------------------------------------
// Kernel 3: rZ[b,i] = 1 / sum_jt Zp[b,jt,i]
// ---------------------------------------------------------------------------
__global__ void rz_kernel()
{
    int g = blockIdx.x * blockDim.x + threadIdx.x;
    int b = g >> 12;
    int i = g & 4095;
    float s = 0.0f;
#pragma unroll
    for (int jt = 0; jt < 32; jt++)
        s += g_Zp[((size_t)(b * 32 + jt)) * HW + i];
    g_rZ[g] = 1.0f / s;
}

// ---------------------------------------------------------------------------
// Kernel 3b: fold rZ into V in place:  g_V[b,c,i] *= rZ[b,i]
// ---------------------------------------------------------------------------
__global__ __launch_bounds__(256) void vscale_kernel()
{
    size_t g = (size_t)blockIdx.x * blockDim.x + threadIdx.x;  // float4 index
    int i4 = (int)(g & 1023);
    int c  = (int)((g >> 10) & 255);
    int b  = (int)(g >> 18);
    size_t off = (((size_t)b * CIN + c) * HW) + (size_t)i4 * 4;
    float4 v  = *(float4*)(g_V + off);
    float4 rz = *(const float4*)(g_rZ + (size_t)b * HW + i4 * 4);
    v.x *= rz.x; v.y *= rz.y; v.z *= rz.z; v.w *= rz.w;
    *(float4*)(g_V + off) = v;
}

// ---------------------------------------------------------------------------
// Kernel 4 (tensor cores, tf32), v2b: 4 warps, 64x64 warp tiles.
//   out[b,c,j] = x[b,c,j] + sum_i Vs[b,c,i] * E[b,i,j]
// CTA 128(c) x 128(j), BK=16, warp grid 2x2, warp tile 64x64 (mt=4, nt=8).
// Halves smem-load duplication vs 8-warp/64x32 (LDS was the bottleneck).
// v2b: B (E rows, wide-coalesced) issued before A in copy_stage.
// ---------------------------------------------------------------------------
#define OUT_BK 16
#define A_STRIDE 20
#define B_STRIDE 136

__device__ __forceinline__ void cp16(float* dst_smem, const float* src)
{
    uint32_t d = (uint32_t)__cvta_generic_to_shared(dst_smem);
    asm volatile("cp.async.cg.shared.global [%0], [%1], 16;\n" :: "r"(d), "l"(src));
}

__global__ __launch_bounds__(128, 2) void out_tc_kernel(
    const float* __restrict__ x, float* __restrict__ out)
{
    __shared__ float As[2][128 * A_STRIDE];
    __shared__ float Bs[2][OUT_BK * B_STRIDE];

    const int b  = blockIdx.z;
    const int c0 = blockIdx.y * 128;
    const int j0 = blockIdx.x * 128;
    const int tid  = threadIdx.x;
    const int lane = tid & 31;
    const int warp = tid >> 5;             // 0..3
    const int m_base = (warp >> 1) * 64;   // 0 or 64
    const int n_base = (warp & 1) * 64;    // 0 or 64

    const float* Vb = g_V + (size_t)b * CIN * HW;
    const float* Eb = g_E + (size_t)b * HW * HW;

    float acc[4][8][4];
#pragma unroll
    for (int mt = 0; mt < 4; mt++)
#pragma unroll
        for (int nt = 0; nt < 8; nt++)
#pragma unroll
            for (int r = 0; r < 4; r++) acc[mt][nt][r] = 0.0f;

    auto copy_stage = [&](int s, int i0) {
#pragma unroll
        for (int l = 0; l < 4; l++) {
            int idx = tid + l * 128;          // 0..511
            int k   = idx >> 5;               // 0..15
            int f4  = (idx & 31) << 2;        // 0..124
            cp16(&Bs[s][k * B_STRIDE + f4], Eb + (size_t)(i0 + k) * HW + j0 + f4);
        }
#pragma unroll
        for (int l = 0; l < 4; l++) {
            int idx = tid + l * 128;          // 0..511
            int r   = idx >> 2;               // 0..127
            int f4  = (idx & 3) << 2;         // 0,4,8,12
            cp16(&As[s][r * A_STRIDE + f4], Vb + (size_t)(c0 + r) * HW + i0 + f4);
        }
        asm volatile("cp.async.commit_group;\n");
    };

    copy_stage(0, 0);

    const int NK = HW / OUT_BK;   // 256
    for (int kt = 0; kt < NK; kt++) {
        if (kt + 1 < NK) {
            copy_stage((kt + 1) & 1, (kt + 1) * OUT_BK);
            asm volatile("cp.async.wait_group 1;\n");
        } else {
            asm volatile("cp.async.wait_group 0;\n");
        }
        __syncthreads();

        const float* Ap = As[kt & 1];
        const float* Bp = Bs[kt & 1];

#pragma unroll
        for (int k8 = 0; k8 < 2; k8++) {
            const int kk = k8 * 8;
            uint32_t af[4][4];
            uint32_t bf[8][2];
#pragma unroll
            for (int mt = 0; mt < 4; mt++) {
                int r0 = m_base + mt * 16 + (lane >> 2);
                int kc = kk + (lane & 3);
                af[mt][0] = __float_as_uint(Ap[r0 * A_STRIDE + kc]);
                af[mt][1] = __float_as_uint(Ap[(r0 + 8) * A_STRIDE + kc]);
                af[mt][2] = __float_as_uint(Ap[r0 * A_STRIDE + kc + 4]);
                af[mt][3] = __float_as_uint(Ap[(r0 + 8) * A_STRIDE + kc + 4]);
            }
#pragma unroll
            for (int nt = 0; nt < 8; nt++) {
                int cb = n_base + nt * 8 + (lane >> 2);
                int kr = kk + (lane & 3);
                bf[nt][0] = __float_as_uint(Bp[kr * B_STRIDE + cb]);
                bf[nt][1] = __float_as_uint(Bp[(kr + 4) * B_STRIDE + cb]);
            }
#pragma unroll
            for (int mt = 0; mt < 4; mt++)
#pragma unroll
                for (int nt = 0; nt < 8; nt++) {
                    asm volatile(
                        "mma.sync.aligned.m16n8k8.row.col.f32.tf32.tf32.f32 "
                        "{%0,%1,%2,%3}, {%4,%5,%6,%7}, {%8,%9}, {%0,%1,%2,%3};\n"
                        : "+f"(acc[mt][nt][0]), "+f"(acc[mt][nt][1]),
                          "+f"(acc[mt][nt][2]), "+f"(acc[mt][nt][3])
                        : "r"(af[mt][0]), "r"(af[mt][1]), "r"(af[mt][2]), "r"(af[mt][3]),
                          "r"(bf[nt][0]), "r"(bf[nt][1]));
                }
        }
        __syncthreads();
    }

    // ---- epilogue: residual add + store ----
#pragma unroll
    for (int mt = 0; mt < 4; mt++) {
        int c = c0 + m_base + mt * 16 + (lane >> 2);
#pragma unroll
        for (int nt = 0; nt < 8; nt++) {
            int j = j0 + n_base + nt * 8 + 2 * (lane & 3);
            size_t base0 = ((size_t)b * CIN + c) * HW + j;
            size_t base1 = base0 + (size_t)8 * HW;
            float2 x0 = *(const float2*)(x + base0);
            float2 x1 = *(const float2*)(x + base1);
            float2 r0 = make_float2(acc[mt][nt][0] + x0.x, acc[mt][nt][1] + x0.y);
            float2 r1 = make_float2(acc[mt][nt][2] + x1.x, acc[mt][nt][3] + x1.y);
            *(float2*)(out + base0) = r0;
            *(float2*)(out + base1) = r1;
        }
    }
}

// ---------------------------------------------------------------------------
// Launch
// ---------------------------------------------------------------------------
extern "C" void kernel_launch(void* const* d_in, const int* in_sizes, int n_in,
                              void* d_out, int out_size)
{
    const float* x  = (const float*)d_in[0];
    const float* Wq = (const float*)d_in[1];
    const float* bq = (const float*)d_in[2];
    const float* Wk = (const float*)d_in[3];
    const float* bk = (const float*)d_in[4];
    const float* Wv = (const float*)d_in[5];
    const float* bv = (const float*)d_in[6];
    float* out = (float*)d_out;

    dim3 blk(256);
    proj_kernel<<<dim3(32, 1, BATCH), blk>>>(x, Wq, bq, 0);
    proj_kernel<<<dim3(32, 1, BATCH), blk>>>(x, Wk, bk, 1);
    proj_kernel<<<dim3(32, 4, BATCH), blk>>>(x, Wv, bv, 2);
    split_kernel<<<dim3(2048), blk>>>();
    scores_tc_kernel<<<dim3(32, 32, BATCH), blk>>>();
    rz_kernel<<<dim3(128), blk>>>();
    vscale_kernel<<<dim3(8192), blk>>>();
    out_tc_kernel<<<dim3(32, 2, BATCH), dim3(128)>>>(x, out);
}

// round 12
// speedup vs baseline: 2.8669x; 1.1086x over previous
#include <cuda_runtime.h>
#include <cuda_bf16.h>
#include <cuda_fp16.h>
#include <cstdint>
#include <cstddef>

// Problem constants
#define BATCH 8
#define CIN   256
#define KDIM  64
#define HW    4096
#define FS      4096.0f
#define INV_FS  (1.0f / 4096.0f)

// ---------------------------------------------------------------------------
// Scratch (static __device__ globals)
// ---------------------------------------------------------------------------
__device__ float g_Q [(size_t)BATCH * KDIM * HW];      //  8 MB
__device__ float g_K [(size_t)BATCH * KDIM * HW];      //  8 MB
__device__ float g_V [(size_t)BATCH * CIN  * HW];      // 33 MB  [b][256][4096]
__device__ __half g_Eh[(size_t)BATCH * HW * HW];       // 268 MB E' = exp(S - m_tile), fp16
__device__ float g_Zp[(size_t)BATCH * 32 * HW];        //  4 MB  per-(jt,i) tile sums of E'
__device__ float g_M [(size_t)BATCH * 32 * HW];        //  4 MB  per-(jt,i) tile maxes
__device__ float g_F [(size_t)BATCH * 32 * HW];        //  4 MB  F = exp(m - M_i)/Z_i
// bf16 hi/lo splits of Q,K
__device__ __nv_bfloat16 g_Qh[(size_t)BATCH * HW * KDIM];
__device__ __nv_bfloat16 g_Ql[(size_t)BATCH * HW * KDIM];
__device__ __nv_bfloat16 g_Kh[(size_t)BATCH * HW * KDIM];
__device__ __nv_bfloat16 g_Kl[(size_t)BATCH * HW * KDIM];

// ---------------------------------------------------------------------------
// Kernel 1: 1x1 conv projections (unchanged, proven)
// ---------------------------------------------------------------------------
__global__ __launch_bounds__(256) void proj_kernel(
    const float* __restrict__ x, const float* __restrict__ W,
    const float* __restrict__ bias, int sel)
{
    float* out = (sel == 0) ? g_Q : (sel == 1) ? g_K : g_V;
    const int O  = (sel == 2) ? 256 : 64;
    const int b  = blockIdx.z;
    const int o0 = blockIdx.y * 64;
    const int p0 = blockIdx.x * 128;
    const int tid = threadIdx.x;
    const int ty = tid >> 4;
    const int tx = tid & 15;

    __shared__ float Wt[16][68];
    __shared__ float Xs[16][128];

    float acc[4][8];
#pragma unroll
    for (int m = 0; m < 4; m++)
#pragma unroll
        for (int n = 0; n < 8; n++) acc[m][n] = 0.0f;

    const float* xb = x + (size_t)b * CIN * HW;

    for (int c0 = 0; c0 < CIN; c0 += 16) {
#pragma unroll
        for (int l = 0; l < 4; l++) {
            int e  = tid + l * 256;
            int o  = e >> 4;
            int kk = e & 15;
            Wt[kk][o] = W[(o0 + o) * CIN + c0 + kk];
        }
#pragma unroll
        for (int l = 0; l < 2; l++) {
            int e  = tid + l * 256;
            int kk = e >> 5;
            int p4 = (e & 31) << 2;
            float4 v = *(const float4*)(xb + (size_t)(c0 + kk) * HW + p0 + p4);
            *(float4*)(&Xs[kk][p4]) = v;
        }
        __syncthreads();
#pragma unroll
        for (int kk = 0; kk < 16; kk++) {
            float4 a  = *(const float4*)(&Wt[kk][ty * 4]);
            float4 b0 = *(const float4*)(&Xs[kk][tx * 4]);
            float4 b1 = *(const float4*)(&Xs[kk][64 + tx * 4]);
            float av[4] = {a.x, a.y, a.z, a.w};
            float bv[8] = {b0.x, b0.y, b0.z, b0.w, b1.x, b1.y, b1.z, b1.w};
#pragma unroll
            for (int m = 0; m < 4; m++)
#pragma unroll
                for (int n = 0; n < 8; n++) acc[m][n] += av[m] * bv[n];
        }
        __syncthreads();
    }

#pragma unroll
    for (int m = 0; m < 4; m++) {
        int o = o0 + ty * 4 + m;
        float bo = bias[o];
        size_t base = ((size_t)b * O + o) * HW + p0;
        float4 r0 = make_float4(acc[m][0] + bo, acc[m][1] + bo, acc[m][2] + bo, acc[m][3] + bo);
        float4 r1 = make_float4(acc[m][4] + bo, acc[m][5] + bo, acc[m][6] + bo, acc[m][7] + bo);
        *(float4*)(out + base + tx * 4)      = r0;
        *(float4*)(out + base + 64 + tx * 4) = r1;
    }
}

// ---------------------------------------------------------------------------
// Kernel 1b: split Q,K into bf16 hi/lo pairs (unchanged, proven)
// ---------------------------------------------------------------------------
__global__ __launch_bounds__(256) void split_kernel()
{
    size_t g = (size_t)blockIdx.x * blockDim.x + threadIdx.x;
    size_t off = g * 4;

    float4 q = *(const float4*)(g_Q + off);
    float4 k = *(const float4*)(g_K + off);

    float qv[4] = {q.x, q.y, q.z, q.w};
    float kv[4] = {k.x, k.y, k.z, k.w};
    __nv_bfloat16 qh[4], ql[4], kh[4], kl[4];
#pragma unroll
    for (int e = 0; e < 4; e++) {
        qh[e] = __float2bfloat16_rn(qv[e]);
        ql[e] = __float2bfloat16_rn(qv[e] - __bfloat162float(qh[e]));
        kh[e] = __float2bfloat16_rn(kv[e]);
        kl[e] = __float2bfloat16_rn(kv[e] - __bfloat162float(kh[e]));
    }
    *(uint2*)(g_Qh + off) = *(uint2*)qh;
    *(uint2*)(g_Ql + off) = *(uint2*)ql;
    *(uint2*)(g_Kh + off) = *(uint2*)kh;
    *(uint2*)(g_Kl + off) = *(uint2*)kl;
}

// ---------------------------------------------------------------------------
// Kernel 2 (mma.sync bf16 3-term, proven mainloop) + NEW epilogue:
//   m[i,jt] = rowmax over this CTA's 128 cols; E' = exp(S - m) stored fp16;
//   Zp[i,jt] = sum of E' (of the rounded fp16 values).
// ---------------------------------------------------------------------------
#define QK_STRIDE 40

__global__ __launch_bounds__(256) void scores_tc_kernel()
{
    __shared__ __nv_bfloat16 sQh[128][QK_STRIDE];
    __shared__ __nv_bfloat16 sQl[128][QK_STRIDE];
    __shared__ __nv_bfloat16 sKh[128][QK_STRIDE];
    __shared__ __nv_bfloat16 sKl[128][QK_STRIDE];
    __shared__ float Zbuf[128][4];
    __shared__ float Mbuf[128][4];

    const int b  = blockIdx.z;
    const int i0 = blockIdx.y * 128;
    const int j0 = blockIdx.x * 128;
    const int jt = blockIdx.x;
    const int tid  = threadIdx.x;
    const int lane = tid & 31;
    const int warp = tid >> 5;
    const int m_base = (warp >> 2) * 64;
    const int wn     = warp & 3;
    const int n_base = wn * 32;

    const __nv_bfloat16* Qh = g_Qh + (size_t)b * HW * KDIM;
    const __nv_bfloat16* Ql = g_Ql + (size_t)b * HW * KDIM;
    const __nv_bfloat16* Kh = g_Kh + (size_t)b * HW * KDIM;
    const __nv_bfloat16* Kl = g_Kl + (size_t)b * HW * KDIM;

    float acc[4][4][4];
#pragma unroll
    for (int mt = 0; mt < 4; mt++)
#pragma unroll
        for (int nt = 0; nt < 4; nt++)
#pragma unroll
            for (int r = 0; r < 4; r++) acc[mt][nt][r] = 0.0f;

    for (int d0 = 0; d0 < KDIM; d0 += 32) {
#pragma unroll
        for (int l = 0; l < 2; l++) {
            int idx = tid + l * 256;
            int r   = idx >> 2;
            int f8  = (idx & 3) << 3;
            size_t qoff = ((size_t)(i0 + r)) * KDIM + d0 + f8;
            size_t koff = ((size_t)(j0 + r)) * KDIM + d0 + f8;
            *(uint4*)(&sQh[r][f8]) = *(const uint4*)(Qh + qoff);
            *(uint4*)(&sQl[r][f8]) = *(const uint4*)(Ql + qoff);
            *(uint4*)(&sKh[r][f8]) = *(const uint4*)(Kh + koff);
            *(uint4*)(&sKl[r][f8]) = *(const uint4*)(Kl + koff);
        }
        __syncthreads();

#pragma unroll
        for (int k16 = 0; k16 < 2; k16++) {
            const int kk = k16 * 16;
            const int kc = kk + (lane & 3) * 2;
            const int rA = lane >> 2;

            uint32_t ah[4][4], al[4][4];
#pragma unroll
            for (int mt = 0; mt < 4; mt++) {
                int r0 = m_base + mt * 16 + rA;
                ah[mt][0] = *(const uint32_t*)(&sQh[r0][kc]);
                ah[mt][1] = *(const uint32_t*)(&sQh[r0 + 8][kc]);
                ah[mt][2] = *(const uint32_t*)(&sQh[r0][kc + 8]);
                ah[mt][3] = *(const uint32_t*)(&sQh[r0 + 8][kc + 8]);
                al[mt][0] = *(const uint32_t*)(&sQl[r0][kc]);
                al[mt][1] = *(const uint32_t*)(&sQl[r0 + 8][kc]);
                al[mt][2] = *(const uint32_t*)(&sQl[r0][kc + 8]);
                al[mt][3] = *(const uint32_t*)(&sQl[r0 + 8][kc + 8]);
            }
            uint32_t bh[4][2], bl[4][2];
#pragma unroll
            for (int nt = 0; nt < 4; nt++) {
                int j = n_base + nt * 8 + rA;
                bh[nt][0] = *(const uint32_t*)(&sKh[j][kc]);
                bh[nt][1] = *(const uint32_t*)(&sKh[j][kc + 8]);
                bl[nt][0] = *(const uint32_t*)(&sKl[j][kc]);
                bl[nt][1] = *(const uint32_t*)(&sKl[j][kc + 8]);
            }
#pragma unroll
            for (int mt = 0; mt < 4; mt++)
#pragma unroll
                for (int nt = 0; nt < 4; nt++) {
#define BF16MMA(AF, BF)                                                         \
    asm volatile(                                                               \
        "mma.sync.aligned.m16n8k16.row.col.f32.bf16.bf16.f32 "                  \
        "{%0,%1,%2,%3}, {%4,%5,%6,%7}, {%8,%9}, {%0,%1,%2,%3};\n"               \
        : "+f"(acc[mt][nt][0]), "+f"(acc[mt][nt][1]),                           \
          "+f"(acc[mt][nt][2]), "+f"(acc[mt][nt][3])                            \
        : "r"(AF[mt][0]), "r"(AF[mt][1]), "r"(AF[mt][2]), "r"(AF[mt][3]),       \
          "r"(BF[nt][0]), "r"(BF[nt][1]))
                    BF16MMA(ah, bh);
                    BF16MMA(ah, bl);
                    BF16MMA(al, bh);
#undef BF16MMA
                }
        }
        __syncthreads();
    }

    // ---- epilogue v3: rowmax -> exp(S-m) -> fp16 E', tile sums, m ----
    const int rA = lane >> 2;
    const int cB = (lane & 3) * 2;

    // 1) per-(row, warp) max
#pragma unroll
    for (int mt = 0; mt < 4; mt++) {
        float mlo = -1e30f, mhi = -1e30f;
#pragma unroll
        for (int nt = 0; nt < 4; nt++) {
            mlo = fmaxf(mlo, fmaxf(acc[mt][nt][0], acc[mt][nt][1]));
            mhi = fmaxf(mhi, fmaxf(acc[mt][nt][2], acc[mt][nt][3]));
        }
#pragma unroll
        for (int o = 1; o < 4; o <<= 1) {
            mlo = fmaxf(mlo, __shfl_xor_sync(0xffffffffu, mlo, o));
            mhi = fmaxf(mhi, __shfl_xor_sync(0xffffffffu, mhi, o));
        }
        if ((lane & 3) == 0) {
            Mbuf[m_base + mt * 16 + rA][wn]     = mlo;
            Mbuf[m_base + mt * 16 + rA + 8][wn] = mhi;
        }
    }
    __syncthreads();

    // 2) CTA-wide row max, exp, fp16 store, rowsum (of rounded values)
    const size_t Ebase = (size_t)b * HW * HW;
#pragma unroll
    for (int mt = 0; mt < 4; mt++) {
        int r = m_base + mt * 16 + rA;
        float m_lo = fmaxf(fmaxf(Mbuf[r][0], Mbuf[r][1]), fmaxf(Mbuf[r][2], Mbuf[r][3]));
        float m_hi = fmaxf(fmaxf(Mbuf[r + 8][0], Mbuf[r + 8][1]),
                           fmaxf(Mbuf[r + 8][2], Mbuf[r + 8][3]));
        float rs_lo = 0.0f, rs_hi = 0.0f;
#pragma unroll
        for (int nt = 0; nt < 4; nt++) {
            float e0 = __expf(acc[mt][nt][0] - m_lo);
            float e1 = __expf(acc[mt][nt][1] - m_lo);
            float e2 = __expf(acc[mt][nt][2] - m_hi);
            float e3 = __expf(acc[mt][nt][3] - m_hi);
            __half2 h01 = __floats2half2_rn(e0, e1);
            __half2 h23 = __floats2half2_rn(e2, e3);
            int j = j0 + n_base + nt * 8 + cB;
            *(__half2*)(g_Eh + Ebase + (size_t)(i0 + r) * HW + j)     = h01;
            *(__half2*)(g_Eh + Ebase + (size_t)(i0 + r + 8) * HW + j) = h23;
            float2 f01 = __half22float2(h01);
            float2 f23 = __half22float2(h23);
            rs_lo += f01.x + f01.y;
            rs_hi += f23.x + f23.y;
        }
#pragma unroll
        for (int o = 1; o < 4; o <<= 1) {
            rs_lo += __shfl_xor_sync(0xffffffffu, rs_lo, o);
            rs_hi += __shfl_xor_sync(0xffffffffu, rs_hi, o);
        }
        if ((lane & 3) == 0) {
            Zbuf[r][wn]     = rs_lo;
            Zbuf[r + 8][wn] = rs_hi;
        }
    }
    __syncthreads();
    if (tid < 128) {
        float s  = Zbuf[tid][0] + Zbuf[tid][1] + Zbuf[tid][2] + Zbuf[tid][3];
        float mm = fmaxf(fmaxf(Mbuf[tid][0], Mbuf[tid][1]),
                         fmaxf(Mbuf[tid][2], Mbuf[tid][3]));
        size_t o = ((size_t)(b * 32 + jt)) * HW + (i0 + tid);
        g_Zp[o] = s;
        g_M[o]  = mm;
    }
}

// ---------------------------------------------------------------------------
// Kernel 3 v2: F[i,jt] = exp(m[i,jt] - M_i) / Z_i, Z_i = sum_jt exp(m-M)*Zp
// ---------------------------------------------------------------------------
__global__ void rz_kernel()
{
    int g = blockIdx.x * blockDim.x + threadIdx.x;   // 0 .. 8*4096-1
    int b = g >> 12;
    int i = g & 4095;
    size_t base = ((size_t)b * 32) * HW + i;

    float M = -1e30f;
#pragma unroll
    for (int jt = 0; jt < 32; jt++)
        M = fmaxf(M, g_M[base + (size_t)jt * HW]);
    float Z = 0.0f;
#pragma unroll
    for (int jt = 0; jt < 32; jt++)
        Z += __expf(g_M[base + (size_t)jt * HW] - M) * g_Zp[base + (size_t)jt * HW];
    float invZ = 1.0f / Z;
#pragma unroll
    for (int jt = 0; jt < 32; jt++)
        g_F[base + (size_t)jt * HW] = __expf(g_M[base + (size_t)jt * HW] - M) * invZ;
}

// ---------------------------------------------------------------------------
// Kernel 4 v3 (fp16 mma m16n8k16):
//   out[b,c,j] = x[b,c,j] + (1/FS) * sum_i (V[c,i]*F[i,jt]*FS)_fp16 * E'[i,j]_fp16
// CTA 128(c) x 128(j), BK=32, 8 warps (2x4), warp tile 64x32 (scores pattern).
// B (E') double-buffered cp.async; A (V*F -> fp16) LDG-prefetch + STS.
// ---------------------------------------------------------------------------
#define OB_K 32
#define OA_STRIDE 40    // halves (80 B rows; same conflict-free pattern as scores)
#define OB_STRIDE 136   // halves (272 B rows)

__device__ __forceinline__ void cp16h(__half* dst_smem, const __half* src)
{
    uint32_t d = (uint32_t)__cvta_generic_to_shared(dst_smem);
    asm volatile("cp.async.cg.shared.global [%0], [%1], 16;\n" :: "r"(d), "l"(src));
}

__global__ __launch_bounds__(256) void out_fp16_kernel(
    const float* __restrict__ x, float* __restrict__ out)
{
    __shared__ __half As[2][128 * OA_STRIDE];   // 20480 B
    __shared__ __half Bs[2][OB_K * OB_STRIDE];  // 17408 B

    const int b  = blockIdx.z;
    const int jt = blockIdx.x;
    const int c0 = blockIdx.y * 128;
    const int j0 = jt * 128;
    const int tid  = threadIdx.x;
    const int lane = tid & 31;
    const int warp = tid >> 5;
    const int m_base = (warp >> 2) * 64;
    const int n_base = (warp & 3) * 32;

    const float*  Vb = g_V  + (size_t)b * CIN * HW;
    const __half* Eb = g_Eh + (size_t)b * HW * HW;
    const float*  Fb = g_F  + ((size_t)(b * 32 + jt)) * HW;

    // A-fill task mapping: 4 tasks/thread, each = 4 consecutive i of one c-row
    const int ar[4] = { (tid + 0)   >> 3, (tid + 256) >> 3,
                        (tid + 512) >> 3, (tid + 768) >> 3 };
    const int ac[4] = { (tid + 0) & 7, (tid + 256) & 7, (tid + 512) & 7, (tid + 768) & 7 };

    float acc[4][4][4];
#pragma unroll
    for (int mt = 0; mt < 4; mt++)
#pragma unroll
        for (int nt = 0; nt < 4; nt++)
#pragma unroll
            for (int r = 0; r < 4; r++) acc[mt][nt][r] = 0.0f;

    auto fillB = [&](int s, int i0) {
#pragma unroll
        for (int l = 0; l < 2; l++) {
            int idx = tid + l * 256;          // 0..511
            int k   = idx >> 4;               // 0..31
            int sg  = idx & 15;               // 16B segments
            cp16h(&Bs[s][k * OB_STRIDE + sg * 8],
                  Eb + (size_t)(i0 + k) * HW + j0 + sg * 8);
        }
        asm volatile("cp.async.commit_group;\n");
    };
    auto loadA = [&](int i0, float4 (&v)[4], float4 (&f)[4]) {
#pragma unroll
        for (int l = 0; l < 4; l++) {
            v[l] = *(const float4*)(Vb + (size_t)(c0 + ar[l]) * HW + i0 + ac[l] * 4);
            f[l] = *(const float4*)(Fb + i0 + ac[l] * 4);
        }
    };
    auto stsA = [&](int s, float4 (&v)[4], float4 (&f)[4]) {
#pragma unroll
        for (int l = 0; l < 4; l++) {
            __half h[4];
            h[0] = __float2half_rn(v[l].x * f[l].x * FS);
            h[1] = __float2half_rn(v[l].y * f[l].y * FS);
            h[2] = __float2half_rn(v[l].z * f[l].z * FS);
            h[3] = __float2half_rn(v[l].w * f[l].w * FS);
            *(uint2*)(&As[s][ar[l] * OA_STRIDE + ac[l] * 4]) = *(uint2*)h;
        }
    };

    // prologue
    {
        float4 v[4], f[4];
        fillB(0, 0);
        loadA(0, v, f);
        stsA(0, v, f);
        asm volatile("cp.async.wait_group 0;\n");
        __syncthreads();
    }

    const int NK = HW / OB_K;   // 128
    for (int kt = 0; kt < NK; kt++) {
        float4 pv[4], pf[4];
        const bool has_next = (kt + 1 < NK);
        if (has_next) {
            fillB((kt + 1) & 1, (kt + 1) * OB_K);
            loadA((kt + 1) * OB_K, pv, pf);      // LDG latency covered by MMA below
        }

        const __half* Ap = As[kt & 1];
        const __half* Bp = Bs[kt & 1];

#pragma unroll
        for (int k16 = 0; k16 < 2; k16++) {
            const int kk = k16 * 16;
            const int kc = kk + (lane & 3) * 2;
            const int rA = lane >> 2;

            uint32_t af[4][4];
#pragma unroll
            for (int mt = 0; mt < 4; mt++) {
                int r0 = m_base + mt * 16 + rA;
                af[mt][0] = *(const uint32_t*)(&Ap[r0 * OA_STRIDE + kc]);
                af[mt][1] = *(const uint32_t*)(&Ap[(r0 + 8) * OA_STRIDE + kc]);
                af[mt][2] = *(const uint32_t*)(&Ap[r0 * OA_STRIDE + kc + 8]);
                af[mt][3] = *(const uint32_t*)(&Ap[(r0 + 8) * OA_STRIDE + kc + 8]);
            }
            uint32_t bf[4][2];
#pragma unroll
            for (int nt = 0; nt < 4; nt++) {
                int jn = n_base + nt * 8 + rA;
                uint32_t l0 = *(const unsigned short*)(&Bp[(kc)     * OB_STRIDE + jn]);
                uint32_t h0 = *(const unsigned short*)(&Bp[(kc + 1) * OB_STRIDE + jn]);
                uint32_t l1 = *(const unsigned short*)(&Bp[(kc + 8) * OB_STRIDE + jn]);
                uint32_t h1 = *(const unsigned short*)(&Bp[(kc + 9) * OB_STRIDE + jn]);
                bf[nt][0] = l0 | (h0 << 16);
                bf[nt][1] = l1 | (h1 << 16);
            }
#pragma unroll
            for (int mt = 0; mt < 4; mt++)
#pragma unroll
                for (int nt = 0; nt < 4; nt++) {
                    asm volatile(
                        "mma.sync.aligned.m16n8k16.row.col.f32.f16.f16.f32 "
                        "{%0,%1,%2,%3}, {%4,%5,%6,%7}, {%8,%9}, {%0,%1,%2,%3};\n"
                        : "+f"(acc[mt][nt][0]), "+f"(acc[mt][nt][1]),
                          "+f"(acc[mt][nt][2]), "+f"(acc[mt][nt][3])
                        : "r"(af[mt][0]), "r"(af[mt][1]), "r"(af[mt][2]), "r"(af[mt][3]),
                          "r"(bf[nt][0]), "r"(bf[nt][1]));
                }
        }

        if (has_next) {
            stsA((kt + 1) & 1, pv, pf);
            asm volatile("cp.async.wait_group 0;\n");
        }
        __syncthreads();
    }

    // ---- epilogue: 1/FS scale + residual add + store ----
    const int rA = lane >> 2;
    const int cB = (lane & 3) * 2;
#pragma unroll
    for (int mt = 0; mt < 4; mt++) {
        int c = c0 + m_base + mt * 16 + rA;
#pragma unroll
        for (int nt = 0; nt < 4; nt++) {
            int j = j0 + n_base + nt * 8 + cB;
            size_t base0 = ((size_t)b * CIN + c) * HW + j;
            size_t base1 = base0 + (size_t)8 * HW;
            float2 x0 = *(const float2*)(x + base0);
            float2 x1 = *(const float2*)(x + base1);
            float2 r0 = make_float2(acc[mt][nt][0] * INV_FS + x0.x,
                                    acc[mt][nt][1] * INV_FS + x0.y);
            float2 r1 = make_float2(acc[mt][nt][2] * INV_FS + x1.x,
                                    acc[mt][nt][3] * INV_FS + x1.y);
            *(float2*)(out + base0) = r0;
            *(float2*)(out + base1) = r1;
        }
    }
}

// ---------------------------------------------------------------------------
// Launch
// ---------------------------------------------------------------------------
extern "C" void kernel_launch(void* const* d_in, const int* in_sizes, int n_in,
                              void* d_out, int out_size)
{
    const float* x  = (const float*)d_in[0];
    const float* Wq = (const float*)d_in[1];
    const float* bq = (const float*)d_in[2];
    const float* Wk = (const float*)d_in[3];
    const float* bk = (const float*)d_in[4];
    const float* Wv = (const float*)d_in[5];
    const float* bv = (const float*)d_in[6];
    float* out = (float*)d_out;

    dim3 blk(256);
    proj_kernel<<<dim3(32, 1, BATCH), blk>>>(x, Wq, bq, 0);
    proj_kernel<<<dim3(32, 1, BATCH), blk>>>(x, Wk, bk, 1);
    proj_kernel<<<dim3(32, 4, BATCH), blk>>>(x, Wv, bv, 2);
    split_kernel<<<dim3(2048), blk>>>();
    scores_tc_kernel<<<dim3(32, 32, BATCH), blk>>>();
    rz_kernel<<<dim3(128), blk>>>();
    out_fp16_kernel<<<dim3(32, 2, BATCH), blk>>>(x, out);
}

// round 14
// speedup vs baseline: 3.1122x; 1.0856x over previous
#include <cuda_runtime.h>
#include <cuda_bf16.h>
#include <cuda_fp16.h>
#include <cstdint>
#include <cstddef>

// Problem constants
#define BATCH 8
#define CIN   256
#define KDIM  64
#define HW    4096
#define OTOT  384          // concatenated output rows: Q(64) K(64) V(256)
#define FS      4096.0f
#define INV_FS  (1.0f / 4096.0f)

// ---------------------------------------------------------------------------
// Scratch (static __device__ globals)
// ---------------------------------------------------------------------------
__device__ float g_V [(size_t)BATCH * CIN  * HW];      // 33 MB  [b][256][4096]
__device__ __half g_Eh[(size_t)BATCH * HW * HW];       // 268 MB E' = exp(S - m_tile)
__device__ float g_Zp[(size_t)BATCH * 32 * HW];        //  4 MB
__device__ float g_M [(size_t)BATCH * 32 * HW];        //  4 MB
__device__ float g_F [(size_t)BATCH * 32 * HW];        //  4 MB
// bf16 hi/lo splits of Q,K. Flat layout == conv output [b][o][p];
// raw-reshape row i, col d reads flat (i*64+d)  (o*HW+p == (i*64+d))
__device__ __nv_bfloat16 g_Qh[(size_t)BATCH * HW * KDIM];
__device__ __nv_bfloat16 g_Ql[(size_t)BATCH * HW * KDIM];
__device__ __nv_bfloat16 g_Kh[(size_t)BATCH * HW * KDIM];
__device__ __nv_bfloat16 g_Kl[(size_t)BATCH * HW * KDIM];
// bf16 hi/lo splits of x and concatenated W
__device__ __nv_bfloat16 g_xh[(size_t)BATCH * CIN * HW];   // 16.7 MB
__device__ __nv_bfloat16 g_xl[(size_t)BATCH * CIN * HW];
__device__ __nv_bfloat16 g_Wh[OTOT * CIN];
__device__ __nv_bfloat16 g_Wl[OTOT * CIN];
__device__ float         g_bc[OTOT];

// ---------------------------------------------------------------------------
// Kernel 0a: split x into bf16 hi/lo
// ---------------------------------------------------------------------------
__global__ __launch_bounds__(256) void xsplit_kernel(const float* __restrict__ x)
{
    size_t g = (size_t)blockIdx.x * blockDim.x + threadIdx.x;  // one float4
    size_t off = g * 4;   // < 8*256*4096 = 8388608
    float4 v = *(const float4*)(x + off);
    float xv[4] = {v.x, v.y, v.z, v.w};
    __nv_bfloat16 h[4], l[4];
#pragma unroll
    for (int e = 0; e < 4; e++) {
        h[e] = __float2bfloat16_rn(xv[e]);
        l[e] = __float2bfloat16_rn(xv[e] - __bfloat162float(h[e]));
    }
    *(uint2*)(g_xh + off) = *(uint2*)h;
    *(uint2*)(g_xl + off) = *(uint2*)l;
}

// ---------------------------------------------------------------------------
// Kernel 0b: build concatenated W (hi/lo) + bias
// ---------------------------------------------------------------------------
__global__ __launch_bounds__(256) void wsplit_kernel(
    const float* __restrict__ Wq, const float* __restrict__ bq,
    const float* __restrict__ Wk, const float* __restrict__ bk,
    const float* __restrict__ Wv, const float* __restrict__ bv)
{
    int idx = blockIdx.x * 256 + threadIdx.x;   // 0 .. 98303
    if (idx < OTOT * CIN) {
        int row = idx >> 8;       // /256
        int c   = idx & 255;
        float w;
        if (row < 64)       w = Wq[row * CIN + c];
        else if (row < 128) w = Wk[(row - 64) * CIN + c];
        else                w = Wv[(row - 128) * CIN + c];
        __nv_bfloat16 h = __float2bfloat16_rn(w);
        g_Wh[idx] = h;
        g_Wl[idx] = __float2bfloat16_rn(w - __bfloat162float(h));
    }
    if (blockIdx.x == 0 && threadIdx.x < OTOT) {
        int row = threadIdx.x;
        g_bc[row] = (row < 64) ? bq[row] : (row < 128) ? bk[row - 64] : bv[row - 128];
    }
}

// ---------------------------------------------------------------------------
// Kernel 1 (tensor, bf16 3-term): OUT[o,p] = sum_c Wcat[o,c] x[c,p] + b[o]
// CTA 128(o) x 128(p), K=256 in chunks of 32. 8 warps (2x4), warp 64x32.
// Epilogue (FIXED): Q/K stored at conv-flat offset o*HW+p (== raw reshape);
// hi/lo split fused; coalesced 2xbf16 stores. V fp32 coalesced.
// ---------------------------------------------------------------------------
#define PW_STRIDE 40   // W smem stride (halves)
#define PX_STRIDE 34   // x^T smem stride (halves); r*17 mod 32 distinct for 8 rows

__global__ __launch_bounds__(256) void proj_tc_kernel()
{
    __shared__ __nv_bfloat16 sWh[128][PW_STRIDE];
    __shared__ __nv_bfloat16 sWl[128][PW_STRIDE];
    __shared__ __nv_bfloat16 sXh[128][PX_STRIDE];
    __shared__ __nv_bfloat16 sXl[128][PX_STRIDE];

    const int b  = blockIdx.z;
    const int o0 = blockIdx.y * 128;     // 0,128,256
    const int p0 = blockIdx.x * 128;
    const int tid  = threadIdx.x;
    const int lane = tid & 31;
    const int warp = tid >> 5;
    const int m_base = (warp >> 2) * 64;
    const int n_base = (warp & 3) * 32;

    const __nv_bfloat16* xh_b = g_xh + (size_t)b * CIN * HW;
    const __nv_bfloat16* xl_b = g_xl + (size_t)b * CIN * HW;

    float acc[4][4][4];
#pragma unroll
    for (int mt = 0; mt < 4; mt++)
#pragma unroll
        for (int nt = 0; nt < 4; nt++)
#pragma unroll
            for (int r = 0; r < 4; r++) acc[mt][nt][r] = 0.0f;

    for (int c0 = 0; c0 < CIN; c0 += 32) {
        // W tiles: [128 o][32 c], c contiguous
#pragma unroll
        for (int l = 0; l < 2; l++) {
            int idx = tid + l * 256;          // 0..511
            int r   = idx >> 2;               // 0..127
            int f8  = (idx & 3) << 3;         // 0,8,16,24
            *(uint4*)(&sWh[r][f8]) = *(const uint4*)(g_Wh + (o0 + r) * CIN + c0 + f8);
            *(uint4*)(&sWl[r][f8]) = *(const uint4*)(g_Wl + (o0 + r) * CIN + c0 + f8);
        }
        // x tiles transposed: global [c][p] -> smem [p][c]
#pragma unroll
        for (int l = 0; l < 2; l++) {
            int idx = tid + l * 256;          // 0..511
            int c   = idx >> 4;               // 0..31
            int p8  = (idx & 15) << 3;        // 0..120
            size_t go = (size_t)(c0 + c) * HW + p0 + p8;
            uint4 vh = *(const uint4*)(xh_b + go);
            uint4 vl = *(const uint4*)(xl_b + go);
            __nv_bfloat16 th[8], tl[8];
            *(uint4*)th = vh;
            *(uint4*)tl = vl;
#pragma unroll
            for (int e = 0; e < 8; e++) {
                sXh[p8 + e][c] = th[e];
                sXl[p8 + e][c] = tl[e];
            }
        }
        __syncthreads();

#pragma unroll
        for (int k16 = 0; k16 < 2; k16++) {
            const int kk = k16 * 16;
            const int kc = kk + (lane & 3) * 2;
            const int rA = lane >> 2;

            uint32_t ah[4][4], al[4][4];
#pragma unroll
            for (int mt = 0; mt < 4; mt++) {
                int r0 = m_base + mt * 16 + rA;
                ah[mt][0] = *(const uint32_t*)(&sWh[r0][kc]);
                ah[mt][1] = *(const uint32_t*)(&sWh[r0 + 8][kc]);
                ah[mt][2] = *(const uint32_t*)(&sWh[r0][kc + 8]);
                ah[mt][3] = *(const uint32_t*)(&sWh[r0 + 8][kc + 8]);
                al[mt][0] = *(const uint32_t*)(&sWl[r0][kc]);
                al[mt][1] = *(const uint32_t*)(&sWl[r0 + 8][kc]);
                al[mt][2] = *(const uint32_t*)(&sWl[r0][kc + 8]);
                al[mt][3] = *(const uint32_t*)(&sWl[r0 + 8][kc + 8]);
            }
            uint32_t bh[4][2], bl[4][2];
#pragma unroll
            for (int nt = 0; nt < 4; nt++) {
                int j = n_base + nt * 8 + rA;
                bh[nt][0] = *(const uint32_t*)(&sXh[j][kc]);
                bh[nt][1] = *(const uint32_t*)(&sXh[j][kc + 8]);
                bl[nt][0] = *(const uint32_t*)(&sXl[j][kc]);
                bl[nt][1] = *(const uint32_t*)(&sXl[j][kc + 8]);
            }
#pragma unroll
            for (int mt = 0; mt < 4; mt++)
#pragma unroll
                for (int nt = 0; nt < 4; nt++) {
#define BF16MMA(AF, BF)                                                         \
    asm volatile(                                                               \
        "mma.sync.aligned.m16n8k16.row.col.f32.bf16.bf16.f32 "                  \
        "{%0,%1,%2,%3}, {%4,%5,%6,%7}, {%8,%9}, {%0,%1,%2,%3};\n"               \
        : "+f"(acc[mt][nt][0]), "+f"(acc[mt][nt][1]),                           \
          "+f"(acc[mt][nt][2]), "+f"(acc[mt][nt][3])                            \
        : "r"(AF[mt][0]), "r"(AF[mt][1]), "r"(AF[mt][2]), "r"(AF[mt][3]),       \
          "r"(BF[nt][0]), "r"(BF[nt][1]))
                    BF16MMA(ah, bh);
                    BF16MMA(ah, bl);
                    BF16MMA(al, bh);
#undef BF16MMA
                }
        }
        __syncthreads();
    }

    // ---- epilogue (FIXED layout) ----
    const int rA = lane >> 2;
    const int cB = (lane & 3) * 2;

#pragma unroll
    for (int mt = 0; mt < 4; mt++) {
        int ol0 = m_base + mt * 16 + rA;       // local row (and +8)
        float b0 = g_bc[o0 + ol0];
        float b1 = g_bc[o0 + ol0 + 8];
#pragma unroll
        for (int nt = 0; nt < 4; nt++) {
            int p = p0 + n_base + nt * 8 + cB;   // even
            float v00 = acc[mt][nt][0] + b0;
            float v01 = acc[mt][nt][1] + b0;
            float v10 = acc[mt][nt][2] + b1;
            float v11 = acc[mt][nt][3] + b1;
            if (o0 == 0) {
                // Q (o<64) / K (64..127): conv-flat layout o*HW + p (== raw reshape).
                // Contiguous pair (p, p+1): packed 2xbf16 stores.
#pragma unroll
                for (int half = 0; half < 2; half++) {
                    int ol = ol0 + half * 8;
                    float va = half ? v10 : v00;
                    float vb = half ? v11 : v01;
                    __nv_bfloat16* dh = (ol < 64) ? g_Qh : g_Kh;
                    __nv_bfloat16* dl = (ol < 64) ? g_Ql : g_Kl;
                    int oc = ol & 63;
                    size_t off = (size_t)b * HW * KDIM + (size_t)oc * HW + p;
                    __nv_bfloat16 ha = __float2bfloat16_rn(va);
                    __nv_bfloat16 hb = __float2bfloat16_rn(vb);
                    __nv_bfloat16 la = __float2bfloat16_rn(va - __bfloat162float(ha));
                    __nv_bfloat16 lb = __float2bfloat16_rn(vb - __bfloat162float(hb));
                    __nv_bfloat16 hp[2] = {ha, hb};
                    __nv_bfloat16 lp[2] = {la, lb};
                    *(uint32_t*)(dh + off) = *(uint32_t*)hp;
                    *(uint32_t*)(dl + off) = *(uint32_t*)lp;
                }
            } else {
                // V: o-128 = channel, coalesced float2 along p
                int c_ch0 = o0 - 128 + ol0;
                *(float2*)(g_V + ((size_t)b * CIN + c_ch0) * HW + p)     = make_float2(v00, v01);
                *(float2*)(g_V + ((size_t)b * CIN + c_ch0 + 8) * HW + p) = make_float2(v10, v11);
            }
        }
    }
}

// ---------------------------------------------------------------------------
// Kernel 2 (mma.sync bf16 3-term) + fp16 E' epilogue  (unchanged, proven)
// ---------------------------------------------------------------------------
#define QK_STRIDE 40

__global__ __launch_bounds__(256) void scores_tc_kernel()
{
    __shared__ __nv_bfloat16 sQh[128][QK_STRIDE];
    __shared__ __nv_bfloat16 sQl[128][QK_STRIDE];
    __shared__ __nv_bfloat16 sKh[128][QK_STRIDE];
    __shared__ __nv_bfloat16 sKl[128][QK_STRIDE];
    __shared__ float Zbuf[128][4];
    __shared__ float Mbuf[128][4];

    const int b  = blockIdx.z;
    const int i0 = blockIdx.y * 128;
    const int j0 = blockIdx.x * 128;
    const int jt = blockIdx.x;
    const int tid  = threadIdx.x;
    const int lane = tid & 31;
    const int warp = tid >> 5;
    const int m_base = (warp >> 2) * 64;
    const int wn     = warp & 3;
    const int n_base = wn * 32;

    const __nv_bfloat16* Qh = g_Qh + (size_t)b * HW * KDIM;
    const __nv_bfloat16* Ql = g_Ql + (size_t)b * HW * KDIM;
    const __nv_bfloat16* Kh = g_Kh + (size_t)b * HW * KDIM;
    const __nv_bfloat16* Kl = g_Kl + (size_t)b * HW * KDIM;

    float acc[4][4][4];
#pragma unroll
    for (int mt = 0; mt < 4; mt++)
#pragma unroll
        for (int nt = 0; nt < 4; nt++)
#pragma unroll
            for (int r = 0; r < 4; r++) acc[mt][nt][r] = 0.0f;

    for (int d0 = 0; d0 < KDIM; d0 += 32) {
#pragma unroll
        for (int l = 0; l < 2; l++) {
            int idx = tid + l * 256;
            int r   = idx >> 2;
            int f8  = (idx & 3) << 3;
            size_t qoff = ((size_t)(i0 + r)) * KDIM + d0 + f8;
            size_t koff = ((size_t)(j0 + r)) * KDIM + d0 + f8;
            *(uint4*)(&sQh[r][f8]) = *(const uint4*)(Qh + qoff);
            *(uint4*)(&sQl[r][f8]) = *(const uint4*)(Ql + qoff);
            *(uint4*)(&sKh[r][f8]) = *(const uint4*)(Kh + koff);
            *(uint4*)(&sKl[r][f8]) = *(const uint4*)(Kl + koff);
        }
        __syncthreads();

#pragma unroll
        for (int k16 = 0; k16 < 2; k16++) {
            const int kk = k16 * 16;
            const int kc = kk + (lane & 3) * 2;
            const int rA = lane >> 2;

            uint32_t ah[4][4], al[4][4];
#pragma unroll
            for (int mt = 0; mt < 4; mt++) {
                int r0 = m_base + mt * 16 + rA;
                ah[mt][0] = *(const uint32_t*)(&sQh[r0][kc]);
                ah[mt][1] = *(const uint32_t*)(&sQh[r0 + 8][kc]);
                ah[mt][2] = *(const uint32_t*)(&sQh[r0][kc + 8]);
                ah[mt][3] = *(const uint32_t*)(&sQh[r0 + 8][kc + 8]);
                al[mt][0] = *(const uint32_t*)(&sQl[r0][kc]);
                al[mt][1] = *(const uint32_t*)(&sQl[r0 + 8][kc]);
                al[mt][2] = *(const uint32_t*)(&sQl[r0][kc + 8]);
                al[mt][3] = *(const uint32_t*)(&sQl[r0 + 8][kc + 8]);
            }
            uint32_t bh[4][2], bl[4][2];
#pragma unroll
            for (int nt = 0; nt < 4; nt++) {
                int j = n_base + nt * 8 + rA;
                bh[nt][0] = *(const uint32_t*)(&sKh[j][kc]);
                bh[nt][1] = *(const uint32_t*)(&sKh[j][kc + 8]);
                bl[nt][0] = *(const uint32_t*)(&sKl[j][kc]);
                bl[nt][1] = *(const uint32_t*)(&sKl[j][kc + 8]);
            }
#pragma unroll
            for (int mt = 0; mt < 4; mt++)
#pragma unroll
                for (int nt = 0; nt < 4; nt++) {
#define BF16MMA(AF, BF)                                                         \
    asm volatile(                                                               \
        "mma.sync.aligned.m16n8k16.row.col.f32.bf16.bf16.f32 "                  \
        "{%0,%1,%2,%3}, {%4,%5,%6,%7}, {%8,%9}, {%0,%1,%2,%3};\n"               \
        : "+f"(acc[mt][nt][0]), "+f"(acc[mt][nt][1]),                           \
          "+f"(acc[mt][nt][2]), "+f"(acc[mt][nt][3])                            \
        : "r"(AF[mt][0]), "r"(AF[mt][1]), "r"(AF[mt][2]), "r"(AF[mt][3]),       \
          "r"(BF[nt][0]), "r"(BF[nt][1]))
                    BF16MMA(ah, bh);
                    BF16MMA(ah, bl);
                    BF16MMA(al, bh);
#undef BF16MMA
                }
        }
        __syncthreads();
    }

    const int rA = lane >> 2;
    const int cB = (lane & 3) * 2;

#pragma unroll
    for (int mt = 0; mt < 4; mt++) {
        float mlo = -1e30f, mhi = -1e30f;
#pragma unroll
        for (int nt = 0; nt < 4; nt++) {
            mlo = fmaxf(mlo, fmaxf(acc[mt][nt][0], acc[mt][nt][1]));
            mhi = fmaxf(mhi, fmaxf(acc[mt][nt][2], acc[mt][nt][3]));
        }
#pragma unroll
        for (int o = 1; o < 4; o <<= 1) {
            mlo = fmaxf(mlo, __shfl_xor_sync(0xffffffffu, mlo, o));
            mhi = fmaxf(mhi, __shfl_xor_sync(0xffffffffu, mhi, o));
        }
        if ((lane & 3) == 0) {
            Mbuf[m_base + mt * 16 + rA][wn]     = mlo;
            Mbuf[m_base + mt * 16 + rA + 8][wn] = mhi;
        }
    }
    __syncthreads();

    const size_t Ebase = (size_t)b * HW * HW;
#pragma unroll
    for (int mt = 0; mt < 4; mt++) {
        int r = m_base + mt * 16 + rA;
        float m_lo = fmaxf(fmaxf(Mbuf[r][0], Mbuf[r][1]), fmaxf(Mbuf[r][2], Mbuf[r][3]));
        float m_hi = fmaxf(fmaxf(Mbuf[r + 8][0], Mbuf[r + 8][1]),
                           fmaxf(Mbuf[r + 8][2], Mbuf[r + 8][3]));
        float rs_lo = 0.0f, rs_hi = 0.0f;
#pragma unroll
        for (int nt = 0; nt < 4; nt++) {
            float e0 = __expf(acc[mt][nt][0] - m_lo);
            float e1 = __expf(acc[mt][nt][1] - m_lo);
            float e2 = __expf(acc[mt][nt][2] - m_hi);
            float e3 = __expf(acc[mt][nt][3] - m_hi);
            __half2 h01 = __floats2half2_rn(e0, e1);
            __half2 h23 = __floats2half2_rn(e2, e3);
            int j = j0 + n_base + nt * 8 + cB;
            *(__half2*)(g_Eh + Ebase + (size_t)(i0 + r) * HW + j)     = h01;
            *(__half2*)(g_Eh + Ebase + (size_t)(i0 + r + 8) * HW + j) = h23;
            float2 f01 = __half22float2(h01);
            float2 f23 = __half22float2(h23);
            rs_lo += f01.x + f01.y;
            rs_hi += f23.x + f23.y;
        }
#pragma unroll
        for (int o = 1; o < 4; o <<= 1) {
            rs_lo += __shfl_xor_sync(0xffffffffu, rs_lo, o);
            rs_hi += __shfl_xor_sync(0xffffffffu, rs_hi, o);
        }
        if ((lane & 3) == 0) {
            Zbuf[r][wn]     = rs_lo;
            Zbuf[r + 8][wn] = rs_hi;
        }
    }
    __syncthreads();
    if (tid < 128) {
        float s  = Zbuf[tid][0] + Zbuf[tid][1] + Zbuf[tid][2] + Zbuf[tid][3];
        float mm = fmaxf(fmaxf(Mbuf[tid][0], Mbuf[tid][1]),
                         fmaxf(Mbuf[tid][2], Mbuf[tid][3]));
        size_t o = ((size_t)(b * 32 + jt)) * HW + (i0 + tid);
        g_Zp[o] = s;
        g_M[o]  = mm;
    }
}

// ---------------------------------------------------------------------------
// Kernel 3: F = exp(m - M_i)/Z_i  (unchanged, proven)
// ---------------------------------------------------------------------------
__global__ void rz_kernel()
{
    int g = blockIdx.x * blockDim.x + threadIdx.x;
    int b = g >> 12;
    int i = g & 4095;
    size_t base = ((size_t)b * 32) * HW + i;

    float M = -1e30f;
#pragma unroll
    for (int jt = 0; jt < 32; jt++)
        M = fmaxf(M, g_M[base + (size_t)jt * HW]);
    float Z = 0.0f;
#pragma unroll
    for (int jt = 0; jt < 32; jt++)
        Z += __expf(g_M[base + (size_t)jt * HW] - M) * g_Zp[base + (size_t)jt * HW];
    float invZ = 1.0f / Z;
#pragma unroll
    for (int jt = 0; jt < 32; jt++)
        g_F[base + (size_t)jt * HW] = __expf(g_M[base + (size_t)jt * HW] - M) * invZ;
}

// ---------------------------------------------------------------------------
// Kernel 4 (fp16 mma)  (unchanged, proven)
// ---------------------------------------------------------------------------
#define OB_K 32
#define OA_STRIDE 40
#define OB_STRIDE 136

__device__ __forceinline__ void cp16h(__half* dst_smem, const __half* src)
{
    uint32_t d = (uint32_t)__cvta_generic_to_shared(dst_smem);
    asm volatile("cp.async.cg.shared.global [%0], [%1], 16;\n" :: "r"(d), "l"(src));
}

__global__ __launch_bounds__(256) void out_fp16_kernel(
    const float* __restrict__ x, float* __restrict__ out)
{
    __shared__ __half As[2][128 * OA_STRIDE];
    __shared__ __half Bs[2][OB_K * OB_STRIDE];

    const int b  = blockIdx.z;
    const int jt = blockIdx.x;
    const int c0 = blockIdx.y * 128;
    const int j0 = jt * 128;
    const int tid  = threadIdx.x;
    const int lane = tid & 31;
    const int warp = tid >> 5;
    const int m_base = (warp >> 2) * 64;
    const int n_base = (warp & 3) * 32;

    const float*  Vb = g_V  + (size_t)b * CIN * HW;
    const __half* Eb = g_Eh + (size_t)b * HW * HW;
    const float*  Fb = g_F  + ((size_t)(b * 32 + jt)) * HW;

    const int ar[4] = { (tid + 0)   >> 3, (tid + 256) >> 3,
                        (tid + 512) >> 3, (tid + 768) >> 3 };
    const int ac[4] = { (tid + 0) & 7, (tid + 256) & 7, (tid + 512) & 7, (tid + 768) & 7 };

    float acc[4][4][4];
#pragma unroll
    for (int mt = 0; mt < 4; mt++)
#pragma unroll
        for (int nt = 0; nt < 4; nt++)
#pragma unroll
            for (int r = 0; r < 4; r++) acc[mt][nt][r] = 0.0f;

    auto fillB = [&](int s, int i0) {
#pragma unroll
        for (int l = 0; l < 2; l++) {
            int idx = tid + l * 256;
            int k   = idx >> 4;
            int sg  = idx & 15;
            cp16h(&Bs[s][k * OB_STRIDE + sg * 8],
                  Eb + (size_t)(i0 + k) * HW + j0 + sg * 8);
        }
        asm volatile("cp.async.commit_group;\n");
    };
    auto loadA = [&](int i0, float4 (&v)[4], float4 (&f)[4]) {
#pragma unroll
        for (int l = 0; l < 4; l++) {
            v[l] = *(const float4*)(Vb + (size_t)(c0 + ar[l]) * HW + i0 + ac[l] * 4);
            f[l] = *(const float4*)(Fb + i0 + ac[l] * 4);
        }
    };
    auto stsA = [&](int s, float4 (&v)[4], float4 (&f)[4]) {
#pragma unroll
        for (int l = 0; l < 4; l++) {
            __half h[4];
            h[0] = __float2half_rn(v[l].x * f[l].x * FS);
            h[1] = __float2half_rn(v[l].y * f[l].y * FS);
            h[2] = __float2half_rn(v[l].z * f[l].z * FS);
            h[3] = __float2half_rn(v[l].w * f[l].w * FS);
            *(uint2*)(&As[s][ar[l] * OA_STRIDE + ac[l] * 4]) = *(uint2*)h;
        }
    };

    {
        float4 v[4], f[4];
        fillB(0, 0);
        loadA(0, v, f);
        stsA(0, v, f);
        asm volatile("cp.async.wait_group 0;\n");
        __syncthreads();
    }

    const int NK = HW / OB_K;
    for (int kt = 0; kt < NK; kt++) {
        float4 pv[4], pf[4];
        const bool has_next = (kt + 1 < NK);
        if (has_next) {
            fillB((kt + 1) & 1, (kt + 1) * OB_K);
            loadA((kt + 1) * OB_K, pv, pf);
        }

        const __half* Ap = As[kt & 1];
        const __half* Bp = Bs[kt & 1];

#pragma unroll
        for (int k16 = 0; k16 < 2; k16++) {
            const int kk = k16 * 16;
            const int kc = kk + (lane & 3) * 2;
            const int rA = lane >> 2;

            uint32_t af[4][4];
#pragma unroll
            for (int mt = 0; mt < 4; mt++) {
                int r0 = m_base + mt * 16 + rA;
                af[mt][0] = *(const uint32_t*)(&Ap[r0 * OA_STRIDE + kc]);
                af[mt][1] = *(const uint32_t*)(&Ap[(r0 + 8) * OA_STRIDE + kc]);
                af[mt][2] = *(const uint32_t*)(&Ap[r0 * OA_STRIDE + kc + 8]);
                af[mt][3] = *(const uint32_t*)(&Ap[(r0 + 8) * OA_STRIDE + kc + 8]);
            }
            uint32_t bf[4][2];
#pragma unroll
            for (int nt = 0; nt < 4; nt++) {
                int jn = n_base + nt * 8 + rA;
                uint32_t l0 = *(const unsigned short*)(&Bp[(kc)     * OB_STRIDE + jn]);
                uint32_t h0 = *(const unsigned short*)(&Bp[(kc + 1) * OB_STRIDE + jn]);
                uint32_t l1 = *(const unsigned short*)(&Bp[(kc + 8) * OB_STRIDE + jn]);
                uint32_t h1 = *(const unsigned short*)(&Bp[(kc + 9) * OB_STRIDE + jn]);
                bf[nt][0] = l0 | (h0 << 16);
                bf[nt][1] = l1 | (h1 << 16);
            }
#pragma unroll
            for (int mt = 0; mt < 4; mt++)
#pragma unroll
                for (int nt = 0; nt < 4; nt++) {
                    asm volatile(
                        "mma.sync.aligned.m16n8k16.row.col.f32.f16.f16.f32 "
                        "{%0,%1,%2,%3}, {%4,%5,%6,%7}, {%8,%9}, {%0,%1,%2,%3};\n"
                        : "+f"(acc[mt][nt][0]), "+f"(acc[mt][nt][1]),
                          "+f"(acc[mt][nt][2]), "+f"(acc[mt][nt][3])
                        : "r"(af[mt][0]), "r"(af[mt][1]), "r"(af[mt][2]), "r"(af[mt][3]),
                          "r"(bf[nt][0]), "r"(bf[nt][1]));
                }
        }

        if (has_next) {
            stsA((kt + 1) & 1, pv, pf);
            asm volatile("cp.async.wait_group 0;\n");
        }
        __syncthreads();
    }

    const int rA = lane >> 2;
    const int cB = (lane & 3) * 2;
#pragma unroll
    for (int mt = 0; mt < 4; mt++) {
        int c = c0 + m_base + mt * 16 + rA;
#pragma unroll
        for (int nt = 0; nt < 4; nt++) {
            int j = j0 + n_base + nt * 8 + cB;
            size_t base0 = ((size_t)b * CIN + c) * HW + j;
            size_t base1 = base0 + (size_t)8 * HW;
            float2 x0 = *(const float2*)(x + base0);
            float2 x1 = *(const float2*)(x + base1);
            float2 r0 = make_float2(acc[mt][nt][0] * INV_FS + x0.x,
                                    acc[mt][nt][1] * INV_FS + x0.y);
            float2 r1 = make_float2(acc[mt][nt][2] * INV_FS + x1.x,
                                    acc[mt][nt][3] * INV_FS + x1.y);
            *(float2*)(out + base0) = r0;
            *(float2*)(out + base1) = r1;
        }
    }
}

// ---------------------------------------------------------------------------
// Launch
// ---------------------------------------------------------------------------
extern "C" void kernel_launch(void* const* d_in, const int* in_sizes, int n_in,
                              void* d_out, int out_size)
{
    const float* x  = (const float*)d_in[0];
    const float* Wq = (const float*)d_in[1];
    const float* bq = (const float*)d_in[2];
    const float* Wk = (const float*)d_in[3];
    const float* bk = (const float*)d_in[4];
    const float* Wv = (const float*)d_in[5];
    const float* bv = (const float*)d_in[6];
    float* out = (float*)d_out;

    dim3 blk(256);
    xsplit_kernel<<<dim3(8192), blk>>>(x);
    wsplit_kernel<<<dim3(384), blk>>>(Wq, bq, Wk, bk, Wv, bv);
    proj_tc_kernel<<<dim3(32, 3, BATCH), blk>>>();
    scores_tc_kernel<<<dim3(32, 32, BATCH), blk>>>();
    rz_kernel<<<dim3(128), blk>>>();
    out_fp16_kernel<<<dim3(32, 2, BATCH), blk>>>(x, out);
}

// round 16
// speedup vs baseline: 3.2272x; 1.0370x over previous
#include <cuda_runtime.h>
#include <cuda_bf16.h>
#include <cuda_fp16.h>
#include <cstdint>
#include <cstddef>

// Problem constants
#define BATCH 8
#define CIN   256
#define KDIM  64
#define HW    4096
#define OTOT  384
#define FS      4096.0f
#define INV_FS  (1.0f / 4096.0f)

// ---------------------------------------------------------------------------
// Scratch (static __device__ globals)
// ---------------------------------------------------------------------------
__device__ float g_V [(size_t)BATCH * CIN  * HW];
__device__ __half g_Eh[(size_t)BATCH * HW * HW];
__device__ float g_Zp[(size_t)BATCH * 32 * HW];
__device__ float g_M [(size_t)BATCH * 32 * HW];
__device__ float g_F [(size_t)BATCH * 32 * HW];
__device__ __nv_bfloat16 g_Qh[(size_t)BATCH * HW * KDIM];
__device__ __nv_bfloat16 g_Ql[(size_t)BATCH * HW * KDIM];
__device__ __nv_bfloat16 g_Kh[(size_t)BATCH * HW * KDIM];
__device__ __nv_bfloat16 g_Kl[(size_t)BATCH * HW * KDIM];
__device__ __nv_bfloat16 g_xh[(size_t)BATCH * CIN * HW];
__device__ __nv_bfloat16 g_xl[(size_t)BATCH * CIN * HW];
__device__ __nv_bfloat16 g_Wh[OTOT * CIN];
__device__ __nv_bfloat16 g_Wl[OTOT * CIN];
__device__ float         g_bc[OTOT];

// ---------------------------------------------------------------------------
// ldmatrix helpers (row addresses MUST be 16B-aligned)
// ---------------------------------------------------------------------------
__device__ __forceinline__ void ldsm_x4(uint32_t& r0, uint32_t& r1, uint32_t& r2,
                                        uint32_t& r3, const void* p)
{
    uint32_t a = (uint32_t)__cvta_generic_to_shared(p);
    asm volatile("ldmatrix.sync.aligned.m8n8.x4.shared.b16 {%0,%1,%2,%3}, [%4];"
                 : "=r"(r0), "=r"(r1), "=r"(r2), "=r"(r3) : "r"(a));
}
__device__ __forceinline__ void ldsm_x2(uint32_t& r0, uint32_t& r1, const void* p)
{
    uint32_t a = (uint32_t)__cvta_generic_to_shared(p);
    asm volatile("ldmatrix.sync.aligned.m8n8.x2.shared.b16 {%0,%1}, [%2];"
                 : "=r"(r0), "=r"(r1) : "r"(a));
}
__device__ __forceinline__ void ldsm_x2t(uint32_t& r0, uint32_t& r1, const void* p)
{
    uint32_t a = (uint32_t)__cvta_generic_to_shared(p);
    asm volatile("ldmatrix.sync.aligned.m8n8.x2.trans.shared.b16 {%0,%1}, [%2];"
                 : "=r"(r0), "=r"(r1) : "r"(a));
}

// ---------------------------------------------------------------------------
// Kernel 0a: split x into bf16 hi/lo
// ---------------------------------------------------------------------------
__global__ __launch_bounds__(256) void xsplit_kernel(const float* __restrict__ x)
{
    size_t g = (size_t)blockIdx.x * blockDim.x + threadIdx.x;
    size_t off = g * 4;
    float4 v = *(const float4*)(x + off);
    float xv[4] = {v.x, v.y, v.z, v.w};
    __nv_bfloat16 h[4], l[4];
#pragma unroll
    for (int e = 0; e < 4; e++) {
        h[e] = __float2bfloat16_rn(xv[e]);
        l[e] = __float2bfloat16_rn(xv[e] - __bfloat162float(h[e]));
    }
    *(uint2*)(g_xh + off) = *(uint2*)h;
    *(uint2*)(g_xl + off) = *(uint2*)l;
}

// ---------------------------------------------------------------------------
// Kernel 0b: build concatenated W (hi/lo) + bias
// ---------------------------------------------------------------------------
__global__ __launch_bounds__(256) void wsplit_kernel(
    const float* __restrict__ Wq, const float* __restrict__ bq,
    const float* __restrict__ Wk, const float* __restrict__ bk,
    const float* __restrict__ Wv, const float* __restrict__ bv)
{
    int idx = blockIdx.x * 256 + threadIdx.x;
    if (idx < OTOT * CIN) {
        int row = idx >> 8;
        int c   = idx & 255;
        float w;
        if (row < 64)       w = Wq[row * CIN + c];
        else if (row < 128) w = Wk[(row - 64) * CIN + c];
        else                w = Wv[(row - 128) * CIN + c];
        __nv_bfloat16 h = __float2bfloat16_rn(w);
        g_Wh[idx] = h;
        g_Wl[idx] = __float2bfloat16_rn(w - __bfloat162float(h));
    }
    if (blockIdx.x == 0 && threadIdx.x < OTOT) {
        int row = threadIdx.x;
        g_bc[row] = (row < 64) ? bq[row] : (row < 128) ? bk[row - 64] : bv[row - 128];
    }
}

// ---------------------------------------------------------------------------
// Kernel 1 (tensor, bf16 3-term): OUT[o,p] = sum_c Wcat[o,c] x[c,p] + b[o]
// FIX: x tile kept in natural [c][p] layout (stride 136 halves = 272B,
// 16B-aligned rows); B-fragments via ldmatrix.x2.trans (out-kernel pattern).
// ---------------------------------------------------------------------------
#define PW_STRIDE 40    // 80 B rows (16B-aligned)
#define PXN_STRIDE 136  // 272 B rows (16B-aligned; 17r mod 8 distinct)

__global__ __launch_bounds__(256) void proj_tc_kernel()
{
    __shared__ __align__(16) __nv_bfloat16 sWh[128][PW_STRIDE];
    __shared__ __align__(16) __nv_bfloat16 sWl[128][PW_STRIDE];
    __shared__ __align__(16) __nv_bfloat16 sXh[32][PXN_STRIDE];
    __shared__ __align__(16) __nv_bfloat16 sXl[32][PXN_STRIDE];

    const int b  = blockIdx.z;
    const int o0 = blockIdx.y * 128;
    const int p0 = blockIdx.x * 128;
    const int tid  = threadIdx.x;
    const int lane = tid & 31;
    const int warp = tid >> 5;
    const int m_base = (warp >> 2) * 64;
    const int n_base = (warp & 3) * 32;

    const __nv_bfloat16* xh_b = g_xh + (size_t)b * CIN * HW;
    const __nv_bfloat16* xl_b = g_xl + (size_t)b * CIN * HW;

    float acc[4][4][4];
#pragma unroll
    for (int mt = 0; mt < 4; mt++)
#pragma unroll
        for (int nt = 0; nt < 4; nt++)
#pragma unroll
            for (int r = 0; r < 4; r++) acc[mt][nt][r] = 0.0f;

    for (int c0 = 0; c0 < CIN; c0 += 32) {
        // W tiles: [128 o][32 c]
#pragma unroll
        for (int l = 0; l < 2; l++) {
            int idx = tid + l * 256;
            int r   = idx >> 2;
            int f8  = (idx & 3) << 3;
            *(uint4*)(&sWh[r][f8]) = *(const uint4*)(g_Wh + (o0 + r) * CIN + c0 + f8);
            *(uint4*)(&sWl[r][f8]) = *(const uint4*)(g_Wl + (o0 + r) * CIN + c0 + f8);
        }
        // x tiles NATURAL [32 c][128 p]: coalesced uint4 (512 tasks)
#pragma unroll
        for (int l = 0; l < 2; l++) {
            int idx = tid + l * 256;          // 0..511
            int c   = idx >> 4;               // 0..31
            int p8  = (idx & 15) << 3;        // 0..120
            size_t go = (size_t)(c0 + c) * HW + p0 + p8;
            *(uint4*)(&sXh[c][p8]) = *(const uint4*)(xh_b + go);
            *(uint4*)(&sXl[c][p8]) = *(const uint4*)(xl_b + go);
        }
        __syncthreads();

#pragma unroll
        for (int k16 = 0; k16 < 2; k16++) {
            const int kk = k16 * 16;
            const int arow = m_base + (lane & 15);
            const int acol = kk + ((lane >> 4) << 3);
            uint32_t ah[4][4], al[4][4];
#pragma unroll
            for (int mt = 0; mt < 4; mt++) {
                ldsm_x4(ah[mt][0], ah[mt][1], ah[mt][2], ah[mt][3], &sWh[arow + mt * 16][acol]);
                ldsm_x4(al[mt][0], al[mt][1], al[mt][2], al[mt][3], &sWl[arow + mt * 16][acol]);
            }
            // B: [c][p] layout -> x2.trans, row = kk + (lane&15) over c, col = n tile
            const int btr = kk + (lane & 15);
            uint32_t bh[4][2], bl[4][2];
#pragma unroll
            for (int nt = 0; nt < 4; nt++) {
                ldsm_x2t(bh[nt][0], bh[nt][1], &sXh[btr][n_base + nt * 8]);
                ldsm_x2t(bl[nt][0], bl[nt][1], &sXl[btr][n_base + nt * 8]);
            }
#pragma unroll
            for (int mt = 0; mt < 4; mt++)
#pragma unroll
                for (int nt = 0; nt < 4; nt++) {
#define BF16MMA(AF, BF)                                                         \
    asm volatile(                                                               \
        "mma.sync.aligned.m16n8k16.row.col.f32.bf16.bf16.f32 "                  \
        "{%0,%1,%2,%3}, {%4,%5,%6,%7}, {%8,%9}, {%0,%1,%2,%3};\n"               \
        : "+f"(acc[mt][nt][0]), "+f"(acc[mt][nt][1]),                           \
          "+f"(acc[mt][nt][2]), "+f"(acc[mt][nt][3])                            \
        : "r"(AF[mt][0]), "r"(AF[mt][1]), "r"(AF[mt][2]), "r"(AF[mt][3]),       \
          "r"(BF[nt][0]), "r"(BF[nt][1]))
                    BF16MMA(ah, bh);
                    BF16MMA(ah, bl);
                    BF16MMA(al, bh);
#undef BF16MMA
                }
        }
        __syncthreads();
    }

    const int rA = lane >> 2;
    const int cB = (lane & 3) * 2;

#pragma unroll
    for (int mt = 0; mt < 4; mt++) {
        int ol0 = m_base + mt * 16 + rA;
        float b0 = g_bc[o0 + ol0];
        float b1 = g_bc[o0 + ol0 + 8];
#pragma unroll
        for (int nt = 0; nt < 4; nt++) {
            int p = p0 + n_base + nt * 8 + cB;
            float v00 = acc[mt][nt][0] + b0;
            float v01 = acc[mt][nt][1] + b0;
            float v10 = acc[mt][nt][2] + b1;
            float v11 = acc[mt][nt][3] + b1;
            if (o0 == 0) {
                // Q/K: conv-flat layout o*HW + p (== raw reshape); packed 2xbf16
#pragma unroll
                for (int half = 0; half < 2; half++) {
                    int ol = ol0 + half * 8;
                    float va = half ? v10 : v00;
                    float vb = half ? v11 : v01;
                    __nv_bfloat16* dh = (ol < 64) ? g_Qh : g_Kh;
                    __nv_bfloat16* dl = (ol < 64) ? g_Ql : g_Kl;
                    int oc = ol & 63;
                    size_t off = (size_t)b * HW * KDIM + (size_t)oc * HW + p;
                    __nv_bfloat16 ha = __float2bfloat16_rn(va);
                    __nv_bfloat16 hb = __float2bfloat16_rn(vb);
                    __nv_bfloat16 la = __float2bfloat16_rn(va - __bfloat162float(ha));
                    __nv_bfloat16 lb = __float2bfloat16_rn(vb - __bfloat162float(hb));
                    __nv_bfloat16 hp[2] = {ha, hb};
                    __nv_bfloat16 lp[2] = {la, lb};
                    *(uint32_t*)(dh + off) = *(uint32_t*)hp;
                    *(uint32_t*)(dl + off) = *(uint32_t*)lp;
                }
            } else {
                int c_ch0 = o0 - 128 + ol0;
                *(float2*)(g_V + ((size_t)b * CIN + c_ch0) * HW + p)     = make_float2(v00, v01);
                *(float2*)(g_V + ((size_t)b * CIN + c_ch0 + 8) * HW + p) = make_float2(v10, v11);
            }
        }
    }
}

// ---------------------------------------------------------------------------
// Kernel 2 (bf16 3-term, ldmatrix fragments) + fp16 E' epilogue
// ---------------------------------------------------------------------------
#define QK_STRIDE 40   // 80 B rows, 16B-aligned

__global__ __launch_bounds__(256) void scores_tc_kernel()
{
    __shared__ __align__(16) __nv_bfloat16 sQh[128][QK_STRIDE];
    __shared__ __align__(16) __nv_bfloat16 sQl[128][QK_STRIDE];
    __shared__ __align__(16) __nv_bfloat16 sKh[128][QK_STRIDE];
    __shared__ __align__(16) __nv_bfloat16 sKl[128][QK_STRIDE];
    __shared__ float Zbuf[128][4];
    __shared__ float Mbuf[128][4];

    const int b  = blockIdx.z;
    const int i0 = blockIdx.y * 128;
    const int j0 = blockIdx.x * 128;
    const int jt = blockIdx.x;
    const int tid  = threadIdx.x;
    const int lane = tid & 31;
    const int warp = tid >> 5;
    const int m_base = (warp >> 2) * 64;
    const int wn     = warp & 3;
    const int n_base = wn * 32;

    const __nv_bfloat16* Qh = g_Qh + (size_t)b * HW * KDIM;
    const __nv_bfloat16* Ql = g_Ql + (size_t)b * HW * KDIM;
    const __nv_bfloat16* Kh = g_Kh + (size_t)b * HW * KDIM;
    const __nv_bfloat16* Kl = g_Kl + (size_t)b * HW * KDIM;

    float acc[4][4][4];
#pragma unroll
    for (int mt = 0; mt < 4; mt++)
#pragma unroll
        for (int nt = 0; nt < 4; nt++)
#pragma unroll
            for (int r = 0; r < 4; r++) acc[mt][nt][r] = 0.0f;

    for (int d0 = 0; d0 < KDIM; d0 += 32) {
#pragma unroll
        for (int l = 0; l < 2; l++) {
            int idx = tid + l * 256;
            int r   = idx >> 2;
            int f8  = (idx & 3) << 3;
            size_t qoff = ((size_t)(i0 + r)) * KDIM + d0 + f8;
            size_t koff = ((size_t)(j0 + r)) * KDIM + d0 + f8;
            *(uint4*)(&sQh[r][f8]) = *(const uint4*)(Qh + qoff);
            *(uint4*)(&sQl[r][f8]) = *(const uint4*)(Ql + qoff);
            *(uint4*)(&sKh[r][f8]) = *(const uint4*)(Kh + koff);
            *(uint4*)(&sKl[r][f8]) = *(const uint4*)(Kl + koff);
        }
        __syncthreads();

#pragma unroll
        for (int k16 = 0; k16 < 2; k16++) {
            const int kk = k16 * 16;
            const int arow = m_base + (lane & 15);
            const int acol = kk + ((lane >> 4) << 3);
            uint32_t ah[4][4], al[4][4];
#pragma unroll
            for (int mt = 0; mt < 4; mt++) {
                ldsm_x4(ah[mt][0], ah[mt][1], ah[mt][2], ah[mt][3], &sQh[arow + mt * 16][acol]);
                ldsm_x4(al[mt][0], al[mt][1], al[mt][2], al[mt][3], &sQl[arow + mt * 16][acol]);
            }
            const int brow = n_base + (lane & 7);
            const int bcol = kk + (lane & 8);
            uint32_t bh[4][2], bl[4][2];
#pragma unroll
            for (int nt = 0; nt < 4; nt++) {
                ldsm_x2(bh[nt][0], bh[nt][1], &sKh[brow + nt * 8][bcol]);
                ldsm_x2(bl[nt][0], bl[nt][1], &sKl[brow + nt * 8][bcol]);
            }
#pragma unroll
            for (int mt = 0; mt < 4; mt++)
#pragma unroll
                for (int nt = 0; nt < 4; nt++) {
#define BF16MMA(AF, BF)                                                         \
    asm volatile(                                                               \
        "mma.sync.aligned.m16n8k16.row.col.f32.bf16.bf16.f32 "                  \
        "{%0,%1,%2,%3}, {%4,%5,%6,%7}, {%8,%9}, {%0,%1,%2,%3};\n"               \
        : "+f"(acc[mt][nt][0]), "+f"(acc[mt][nt][1]),                           \
          "+f"(acc[mt][nt][2]), "+f"(acc[mt][nt][3])                            \
        : "r"(AF[mt][0]), "r"(AF[mt][1]), "r"(AF[mt][2]), "r"(AF[mt][3]),       \
          "r"(BF[nt][0]), "r"(BF[nt][1]))
                    BF16MMA(ah, bh);
                    BF16MMA(ah, bl);
                    BF16MMA(al, bh);
#undef BF16MMA
                }
        }
        __syncthreads();
    }

    const int rA = lane >> 2;
    const int cB = (lane & 3) * 2;

#pragma unroll
    for (int mt = 0; mt < 4; mt++) {
        float mlo = -1e30f, mhi = -1e30f;
#pragma unroll
        for (int nt = 0; nt < 4; nt++) {
            mlo = fmaxf(mlo, fmaxf(acc[mt][nt][0], acc[mt][nt][1]));
            mhi = fmaxf(mhi, fmaxf(acc[mt][nt][2], acc[mt][nt][3]));
        }
#pragma unroll
        for (int o = 1; o < 4; o <<= 1) {
            mlo = fmaxf(mlo, __shfl_xor_sync(0xffffffffu, mlo, o));
            mhi = fmaxf(mhi, __shfl_xor_sync(0xffffffffu, mhi, o));
        }
        if ((lane & 3) == 0) {
            Mbuf[m_base + mt * 16 + rA][wn]     = mlo;
            Mbuf[m_base + mt * 16 + rA + 8][wn] = mhi;
        }
    }
    __syncthreads();

    const size_t Ebase = (size_t)b * HW * HW;
#pragma unroll
    for (int mt = 0; mt < 4; mt++) {
        int r = m_base + mt * 16 + rA;
        float m_lo = fmaxf(fmaxf(Mbuf[r][0], Mbuf[r][1]), fmaxf(Mbuf[r][2], Mbuf[r][3]));
        float m_hi = fmaxf(fmaxf(Mbuf[r + 8][0], Mbuf[r + 8][1]),
                           fmaxf(Mbuf[r + 8][2], Mbuf[r + 8][3]));
        float rs_lo = 0.0f, rs_hi = 0.0f;
#pragma unroll
        for (int nt = 0; nt < 4; nt++) {
            float e0 = __expf(acc[mt][nt][0] - m_lo);
            float e1 = __expf(acc[mt][nt][1] - m_lo);
            float e2 = __expf(acc[mt][nt][2] - m_hi);
            float e3 = __expf(acc[mt][nt][3] - m_hi);
            __half2 h01 = __floats2half2_rn(e0, e1);
            __half2 h23 = __floats2half2_rn(e2, e3);
            int j = j0 + n_base + nt * 8 + cB;
            *(__half2*)(g_Eh + Ebase + (size_t)(i0 + r) * HW + j)     = h01;
            *(__half2*)(g_Eh + Ebase + (size_t)(i0 + r + 8) * HW + j) = h23;
            float2 f01 = __half22float2(h01);
            float2 f23 = __half22float2(h23);
            rs_lo += f01.x + f01.y;
            rs_hi += f23.x + f23.y;
        }
#pragma unroll
        for (int o = 1; o < 4; o <<= 1) {
            rs_lo += __shfl_xor_sync(0xffffffffu, rs_lo, o);
            rs_hi += __shfl_xor_sync(0xffffffffu, rs_hi, o);
        }
        if ((lane & 3) == 0) {
            Zbuf[r][wn]     = rs_lo;
            Zbuf[r + 8][wn] = rs_hi;
        }
    }
    __syncthreads();
    if (tid < 128) {
        float s  = Zbuf[tid][0] + Zbuf[tid][1] + Zbuf[tid][2] + Zbuf[tid][3];
        float mm = fmaxf(fmaxf(Mbuf[tid][0], Mbuf[tid][1]),
                         fmaxf(Mbuf[tid][2], Mbuf[tid][3]));
        size_t o = ((size_t)(b * 32 + jt)) * HW + (i0 + tid);
        g_Zp[o] = s;
        g_M[o]  = mm;
    }
}

// ---------------------------------------------------------------------------
// Kernel 3: F = exp(m - M_i)/Z_i  (unchanged)
// ---------------------------------------------------------------------------
__global__ void rz_kernel()
{
    int g = blockIdx.x * blockDim.x + threadIdx.x;
    int b = g >> 12;
    int i = g & 4095;
    size_t base = ((size_t)b * 32) * HW + i;

    float M = -1e30f;
#pragma unroll
    for (int jt = 0; jt < 32; jt++)
        M = fmaxf(M, g_M[base + (size_t)jt * HW]);
    float Z = 0.0f;
#pragma unroll
    for (int jt = 0; jt < 32; jt++)
        Z += __expf(g_M[base + (size_t)jt * HW] - M) * g_Zp[base + (size_t)jt * HW];
    float invZ = 1.0f / Z;
#pragma unroll
    for (int jt = 0; jt < 32; jt++)
        g_F[base + (size_t)jt * HW] = __expf(g_M[base + (size_t)jt * HW] - M) * invZ;
}

// ---------------------------------------------------------------------------
// Kernel 4 (fp16 mma, ldmatrix fragments incl. trans for B)
// ---------------------------------------------------------------------------
#define OB_K 32
#define OA_STRIDE 40    // 80 B rows, aligned
#define OB_STRIDE 136   // 272 B rows, aligned

__device__ __forceinline__ void cp16h(__half* dst_smem, const __half* src)
{
    uint32_t d = (uint32_t)__cvta_generic_to_shared(dst_smem);
    asm volatile("cp.async.cg.shared.global [%0], [%1], 16;\n" :: "r"(d), "l"(src));
}

__global__ __launch_bounds__(256) void out_fp16_kernel(
    const float* __restrict__ x, float* __restrict__ out)
{
    __shared__ __align__(16) __half As[2][128 * OA_STRIDE];
    __shared__ __align__(16) __half Bs[2][OB_K * OB_STRIDE];

    const int b  = blockIdx.z;
    const int jt = blockIdx.x;
    const int c0 = blockIdx.y * 128;
    const int j0 = jt * 128;
    const int tid  = threadIdx.x;
    const int lane = tid & 31;
    const int warp = tid >> 5;
    const int m_base = (warp >> 2) * 64;
    const int n_base = (warp & 3) * 32;

    const float*  Vb = g_V  + (size_t)b * CIN * HW;
    const __half* Eb = g_Eh + (size_t)b * HW * HW;
    const float*  Fb = g_F  + ((size_t)(b * 32 + jt)) * HW;

    const int ar[4] = { (tid + 0)   >> 3, (tid + 256) >> 3,
                        (tid + 512) >> 3, (tid + 768) >> 3 };
    const int ac[4] = { (tid + 0) & 7, (tid + 256) & 7, (tid + 512) & 7, (tid + 768) & 7 };

    float acc[4][4][4];
#pragma unroll
    for (int mt = 0; mt < 4; mt++)
#pragma unroll
        for (int nt = 0; nt < 4; nt++)
#pragma unroll
            for (int r = 0; r < 4; r++) acc[mt][nt][r] = 0.0f;

    auto fillB = [&](int s, int i0) {
#pragma unroll
        for (int l = 0; l < 2; l++) {
            int idx = tid + l * 256;
            int k   = idx >> 4;
            int sg  = idx & 15;
            cp16h(&Bs[s][k * OB_STRIDE + sg * 8],
                  Eb + (size_t)(i0 + k) * HW + j0 + sg * 8);
        }
        asm volatile("cp.async.commit_group;\n");
    };
    auto loadA = [&](int i0, float4 (&v)[4], float4 (&f)[4]) {
#pragma unroll
        for (int l = 0; l < 4; l++) {
            v[l] = *(const float4*)(Vb + (size_t)(c0 + ar[l]) * HW + i0 + ac[l] * 4);
            f[l] = *(const float4*)(Fb + i0 + ac[l] * 4);
        }
    };
    auto stsA = [&](int s, float4 (&v)[4], float4 (&f)[4]) {
#pragma unroll
        for (int l = 0; l < 4; l++) {
            __half h[4];
            h[0] = __float2half_rn(v[l].x * f[l].x * FS);
            h[1] = __float2half_rn(v[l].y * f[l].y * FS);
            h[2] = __float2half_rn(v[l].z * f[l].z * FS);
            h[3] = __float2half_rn(v[l].w * f[l].w * FS);
            *(uint2*)(&As[s][ar[l] * OA_STRIDE + ac[l] * 4]) = *(uint2*)h;
        }
    };

    {
        float4 v[4], f[4];
        fillB(0, 0);
        loadA(0, v, f);
        stsA(0, v, f);
        asm volatile("cp.async.wait_group 0;\n");
        __syncthreads();
    }

    const int NK = HW / OB_K;
    for (int kt = 0; kt < NK; kt++) {
        float4 pv[4], pf[4];
        const bool has_next = (kt + 1 < NK);
        if (has_next) {
            fillB((kt + 1) & 1, (kt + 1) * OB_K);
            loadA((kt + 1) * OB_K, pv, pf);
        }

        const __half* Ap = As[kt & 1];
        const __half* Bp = Bs[kt & 1];

#pragma unroll
        for (int k16 = 0; k16 < 2; k16++) {
            const int kk = k16 * 16;
            const int arow = m_base + (lane & 15);
            const int acol = kk + ((lane >> 4) << 3);
            uint32_t af[4][4];
#pragma unroll
            for (int mt = 0; mt < 4; mt++) {
                ldsm_x4(af[mt][0], af[mt][1], af[mt][2], af[mt][3],
                        &Ap[(arow + mt * 16) * OA_STRIDE + acol]);
            }
            const int btr = kk + (lane & 15);
            uint32_t bf[4][2];
#pragma unroll
            for (int nt = 0; nt < 4; nt++) {
                ldsm_x2t(bf[nt][0], bf[nt][1], &Bp[btr * OB_STRIDE + n_base + nt * 8]);
            }
#pragma unroll
            for (int mt = 0; mt < 4; mt++)
#pragma unroll
                for (int nt = 0; nt < 4; nt++) {
                    asm volatile(
                        "mma.sync.aligned.m16n8k16.row.col.f32.f16.f16.f32 "
                        "{%0,%1,%2,%3}, {%4,%5,%6,%7}, {%8,%9}, {%0,%1,%2,%3};\n"
                        : "+f"(acc[mt][nt][0]), "+f"(acc[mt][nt][1]),
                          "+f"(acc[mt][nt][2]), "+f"(acc[mt][nt][3])
                        : "r"(af[mt][0]), "r"(af[mt][1]), "r"(af[mt][2]), "r"(af[mt][3]),
                          "r"(bf[nt][0]), "r"(bf[nt][1]));
                }
        }

        if (has_next) {
            stsA((kt + 1) & 1, pv, pf);
            asm volatile("cp.async.wait_group 0;\n");
        }
        __syncthreads();
    }

    const int rA = lane >> 2;
    const int cB = (lane & 3) * 2;
#pragma unroll
    for (int mt = 0; mt < 4; mt++) {
        int c = c0 + m_base + mt * 16 + rA;
#pragma unroll
        for (int nt = 0; nt < 4; nt++) {
            int j = j0 + n_base + nt * 8 + cB;
            size_t base0 = ((size_t)b * CIN + c) * HW + j;
            size_t base1 = base0 + (size_t)8 * HW;
            float2 x0 = *(const float2*)(x + base0);
            float2 x1 = *(const float2*)(x + base1);
            float2 r0 = make_float2(acc[mt][nt][0] * INV_FS + x0.x,
                                    acc[mt][nt][1] * INV_FS + x0.y);
            float2 r1 = make_float2(acc[mt][nt][2] * INV_FS + x1.x,
                                    acc[mt][nt][3] * INV_FS + x1.y);
            *(float2*)(out + base0) = r0;
            *(float2*)(out + base1) = r1;
        }
    }
}

// ---------------------------------------------------------------------------
// Launch
// ---------------------------------------------------------------------------
extern "C" void kernel_launch(void* const* d_in, const int* in_sizes, int n_in,
                              void* d_out, int out_size)
{
    const float* x  = (const float*)d_in[0];
    const float* Wq = (const float*)d_in[1];
    const float* bq = (const float*)d_in[2];
    const float* Wk = (const float*)d_in[3];
    const float* bk = (const float*)d_in[4];
    const float* Wv = (const float*)d_in[5];
    const float* bv = (const float*)d_in[6];
    float* out = (float*)d_out;

    dim3 blk(256);
    xsplit_kernel<<<dim3(8192), blk>>>(x);
    wsplit_kernel<<<dim3(384), blk>>>(Wq, bq, Wk, bk, Wv, bv);
    proj_tc_kernel<<<dim3(32, 3, BATCH), blk>>>();
    scores_tc_kernel<<<dim3(32, 32, BATCH), blk>>>();
    rz_kernel<<<dim3(128), blk>>>();
    out_fp16_kernel<<<dim3(32, 2, BATCH), blk>>>(x, out);
}